// round 2
// baseline (speedup 1.0000x reference)
#include <cuda_runtime.h>
#include <cuda_bf16.h>
#include <math.h>

// Problem constants
#define BB 2
#define TT 1024
#define CC 2048
#define HH 32
#define NN 64
#define BT (BB*TT)              // 2048
#define BTC (BB*TT*CC)          // 4194304

// ---------------------------------------------------------------------------
// Scratch (static device memory; no allocations anywhere)
// ---------------------------------------------------------------------------
// 18 BTC-sized fp32 buffers + LoRA intermediates
#define N_BIG 18
#define U_W_OFF   ((size_t)N_BIG*BTC)
#define U_A_OFF   (U_W_OFF + (size_t)BT*64)
#define U_V_OFF   (U_A_OFF + (size_t)BT*64)
#define U_G_OFF   (U_V_OFF + (size_t)BT*32)
#define SCRATCH_FLOATS (U_G_OFF + (size_t)BT*128)

__device__ float g_scratch[SCRATCH_FLOATS];

// big-buffer slot indices
enum {
    S_XR=0, S_XW, S_XK, S_XV, S_XA, S_XG,
    S_R, S_K, S_V,
    S_DECAY, S_ASIG, S_G,
    S_AW, S_BW, S_KF, S_VF,
    S_O, S_XO
};

// ---------------------------------------------------------------------------
// K1: token shift + 6-way mix
// ---------------------------------------------------------------------------
__global__ __launch_bounds__(256) void mix_kernel(
    const float* __restrict__ h, const float* __restrict__ shift,
    const float* __restrict__ mr, const float* __restrict__ mw,
    const float* __restrict__ mk, const float* __restrict__ mv,
    const float* __restrict__ ma, const float* __restrict__ mg,
    float* __restrict__ oxr, float* __restrict__ oxw,
    float* __restrict__ oxk, float* __restrict__ oxv,
    float* __restrict__ oxa, float* __restrict__ oxg)
{
    int gid = blockIdx.x * 256 + threadIdx.x;      // 0..1048575
    int row = gid >> 9;                            // 0..2047 (bt)
    int c   = (gid & 511) << 2;
    int t   = row & (TT-1);
    int b   = row >> 10;
    size_t off = (size_t)row * CC + c;

    float4 hv = *(const float4*)&h[off];
    float4 pv;
    if (t == 0) pv = *(const float4*)&shift[(size_t)b*CC + c];
    else        pv = *(const float4*)&h[off - CC];
    float4 xx = make_float4(pv.x-hv.x, pv.y-hv.y, pv.z-hv.z, pv.w-hv.w);

#define DO_MIX(dst, mvec)                                            \
    {   float4 m = *(const float4*)&mvec[c];                         \
        float4 o = make_float4(hv.x + xx.x*m.x, hv.y + xx.y*m.y,     \
                               hv.z + xx.z*m.z, hv.w + xx.w*m.w);    \
        *(float4*)&dst[off] = o; }
    DO_MIX(oxr, mr) DO_MIX(oxw, mw) DO_MIX(oxk, mk)
    DO_MIX(oxv, mv) DO_MIX(oxa, ma) DO_MIX(oxg, mg)
#undef DO_MIX
}

// ---------------------------------------------------------------------------
// K2: big fp32 GEMM  Y[2048,2048] = A[2048,2048] @ Bw[2048,2048]^T
//     128x128 block tile, 8x8 thread tile, BK=16, register prefetch
// ---------------------------------------------------------------------------
__global__ __launch_bounds__(256) void gemm_nt_2048(
    const float* __restrict__ A, const float* __restrict__ Bw,
    float* __restrict__ Y)
{
    __shared__ float As[16][132];
    __shared__ float Bs[16][132];
    const int tid = threadIdx.x;
    const int bm = blockIdx.y << 7;
    const int bn = blockIdx.x << 7;

    float4 pa[2], pb[2];

#define GLOAD(k0)                                                         \
    {   _Pragma("unroll")                                                 \
        for (int i = 0; i < 2; i++) {                                     \
            int lin = tid + (i << 8);                                     \
            int row = lin >> 2, cc = (lin & 3) << 2;                      \
            pa[i] = *(const float4*)&A [(size_t)(bm+row)*CC + (k0) + cc]; \
            pb[i] = *(const float4*)&Bw[(size_t)(bn+row)*CC + (k0) + cc]; \
        } }
#define SSTORE()                                                          \
    {   _Pragma("unroll")                                                 \
        for (int i = 0; i < 2; i++) {                                     \
            int lin = tid + (i << 8);                                     \
            int row = lin >> 2, cc = (lin & 3) << 2;                      \
            As[cc+0][row]=pa[i].x; As[cc+1][row]=pa[i].y;                 \
            As[cc+2][row]=pa[i].z; As[cc+3][row]=pa[i].w;                 \
            Bs[cc+0][row]=pb[i].x; Bs[cc+1][row]=pb[i].y;                 \
            Bs[cc+2][row]=pb[i].z; Bs[cc+3][row]=pb[i].w;                 \
        } }

    float acc[8][8];
#pragma unroll
    for (int i=0;i<8;i++)
#pragma unroll
        for (int j=0;j<8;j++) acc[i][j]=0.f;

    const int m0 = (tid >> 4) << 3;
    const int n0 = (tid & 15) << 3;

    GLOAD(0); SSTORE(); __syncthreads();

    for (int k0 = 16; k0 <= 2048; k0 += 16) {
        if (k0 < 2048) GLOAD(k0);
#pragma unroll
        for (int kk = 0; kk < 16; kk++) {
            float4 a0 = *(const float4*)&As[kk][m0];
            float4 a1 = *(const float4*)&As[kk][m0+4];
            float4 b0 = *(const float4*)&Bs[kk][n0];
            float4 b1 = *(const float4*)&Bs[kk][n0+4];
            float am[8] = {a0.x,a0.y,a0.z,a0.w,a1.x,a1.y,a1.z,a1.w};
            float bv[8] = {b0.x,b0.y,b0.z,b0.w,b1.x,b1.y,b1.z,b1.w};
#pragma unroll
            for (int i=0;i<8;i++)
#pragma unroll
                for (int j=0;j<8;j++)
                    acc[i][j] += am[i]*bv[j];
        }
        __syncthreads();
        if (k0 < 2048) { SSTORE(); __syncthreads(); }
    }
#undef GLOAD
#undef SSTORE

#pragma unroll
    for (int i=0;i<8;i++) {
        float4 v0 = make_float4(acc[i][0],acc[i][1],acc[i][2],acc[i][3]);
        float4 v1 = make_float4(acc[i][4],acc[i][5],acc[i][6],acc[i][7]);
        size_t o = (size_t)(bm+m0+i)*CC + bn + n0;
        *(float4*)&Y[o]   = v0;
        *(float4*)&Y[o+4] = v1;
    }
}

// ---------------------------------------------------------------------------
// K3: LoRA stage 1: U[BT,D] = act( X[BT,2048] @ G[2048,D] )
//     ACT: 0=none, 1=tanh, 2=sigmoid
// ---------------------------------------------------------------------------
template<int D, int ACT>
__global__ __launch_bounds__(256) void lora1_kernel(
    const float* __restrict__ X, const float* __restrict__ G,
    float* __restrict__ U)
{
    constexpr int BM = 16, BK = 32;
    constexpr int STEP = 256 / D;
    constexpr int NR = BM / STEP;            // D/16
    constexpr int NG = (BK*D) / (4*256);     // float4 G loads per thread
    __shared__ float Xs[BK][BM+1];
    __shared__ float Gs[BK][D];

    const int tid = threadIdx.x;
    const int bm = blockIdx.x * BM;
    const int c = tid % D;
    const int rg = tid / D;

    float acc[NR];
#pragma unroll
    for (int i=0;i<NR;i++) acc[i]=0.f;

    for (int k0 = 0; k0 < 2048; k0 += BK) {
        if (tid < 128) {
            int row = tid >> 3, cc = (tid & 7) << 2;
            float4 xv = *(const float4*)&X[(size_t)(bm+row)*CC + k0 + cc];
            Xs[cc+0][row]=xv.x; Xs[cc+1][row]=xv.y;
            Xs[cc+2][row]=xv.z; Xs[cc+3][row]=xv.w;
        }
#pragma unroll
        for (int i=0;i<NG;i++){
            int lin = tid + (i<<8);
            int kr = lin / (D/4);
            int cc = (lin % (D/4)) << 2;
            *(float4*)&Gs[kr][cc] = *(const float4*)&G[(size_t)(k0+kr)*D + cc];
        }
        __syncthreads();
#pragma unroll
        for (int kk=0;kk<BK;kk++){
            float gv = Gs[kk][c];
#pragma unroll
            for (int i=0;i<NR;i++)
                acc[i] += Xs[kk][rg + i*STEP] * gv;
        }
        __syncthreads();
    }
#pragma unroll
    for (int i=0;i<NR;i++){
        float y = acc[i];
        if (ACT==1) y = tanhf(y);
        else if (ACT==2) y = 1.f/(1.f+expf(-y));
        U[(size_t)(bm + rg + i*STEP)*D + c] = y;
    }
}

// ---------------------------------------------------------------------------
// K4: LoRA stage 2 + epilogue.
//   MODE 0: decay = e^{-1/2} * sigmoid(acc + w0)
//   MODE 1: sigmoid(acc + a0)
//   MODE 2: v lerp:  out = vraw + (v_first - vraw)*sigmoid(acc + v0)
//   MODE 3: plain (g path)
// ---------------------------------------------------------------------------
template<int D, int MODE>
__global__ __launch_bounds__(256) void stage2_kernel(
    const float* __restrict__ U, const float* __restrict__ V2,
    const float* __restrict__ bias, float* __restrict__ out,
    const float* __restrict__ e1, const float* __restrict__ e2)
{
    constexpr int ROWS = 32;
    constexpr int NL = (ROWS*D)/(4*256);
    __shared__ float Us[ROWS][D];
    const int tid = threadIdx.x;
    const int row0 = blockIdx.y * ROWS;
    const int c = blockIdx.x * 256 + tid;

#pragma unroll
    for (int i=0;i<NL;i++){
        int lin = tid + (i<<8);
        int rr = lin / (D/4), cc = (lin % (D/4)) << 2;
        *(float4*)&Us[rr][cc] = *(const float4*)&U[(size_t)(row0+rr)*D + cc];
    }
    __syncthreads();

    float acc[ROWS];
#pragma unroll
    for (int r=0;r<ROWS;r++) acc[r]=0.f;

#pragma unroll
    for (int d0=0; d0<D; d0+=4){
        float v0 = V2[(size_t)(d0+0)*CC + c];
        float v1 = V2[(size_t)(d0+1)*CC + c];
        float v2 = V2[(size_t)(d0+2)*CC + c];
        float v3 = V2[(size_t)(d0+3)*CC + c];
#pragma unroll
        for (int r=0;r<ROWS;r++){
            float4 u = *(const float4*)&Us[r][d0];
            acc[r] += u.x*v0 + u.y*v1 + u.z*v2 + u.w*v3;
        }
    }
    float bv = (MODE==3) ? 0.f : bias[c];
#pragma unroll
    for (int r=0;r<ROWS;r++){
        size_t idx = (size_t)(row0+r)*CC + c;
        float y = acc[r] + bv;
        if (MODE==0)      out[idx] = 0.6065306597126334f * (1.f/(1.f+expf(-y)));
        else if (MODE==1) out[idx] = 1.f/(1.f+expf(-y));
        else if (MODE==2) {
            float s = 1.f/(1.f+expf(-y));
            float vr = e1[idx];
            out[idx] = vr + (e2[idx]-vr)*s;
        } else            out[idx] = y;
    }
}

// ---------------------------------------------------------------------------
// K5: per-(b,t,h) prep: normalized kk -> aw=-kk, bw=kk*a, k_final
//     4 heads per 256-thread block
// ---------------------------------------------------------------------------
__global__ __launch_bounds__(256) void prep_kernel(
    const float* __restrict__ k, const float* __restrict__ asig,
    const float* __restrict__ kkvec, const float* __restrict__ kavec,
    float* __restrict__ aw, float* __restrict__ bw, float* __restrict__ kf)
{
    const int tid = threadIdx.x;
    const int g = tid >> 6, n = tid & 63;
    const size_t head = (size_t)blockIdx.x*4 + g;
    const size_t idx = head*64 + n;
    const int c = (int)(idx & (CC-1));

    float kv = k[idx];
    float kk = kv * kkvec[c];
    float ss = kk*kk;
#pragma unroll
    for (int off=16; off; off>>=1) ss += __shfl_xor_sync(0xffffffffu, ss, off);
    __shared__ float red[8];
    if ((tid & 31)==0) red[tid>>5] = ss;
    __syncthreads();
    float tot = red[g*2] + red[g*2+1];
    float inv = 1.f / fmaxf(sqrtf(tot), 1e-12f);
    float kkn = kk * inv;
    float a = asig[idx];
    aw[idx] = -kkn;
    bw[idx] = kkn * a;
    kf[idx] = kv + kavec[c]*(kv*a - kv);
}

// ---------------------------------------------------------------------------
// K6: WKV7 recurrence. One block per (b,h). 128 threads: thread = (v, k-half),
//     S[32] in registers, 2-deep global->smem prefetch.
// ---------------------------------------------------------------------------
__global__ __launch_bounds__(128) void wkv_kernel(
    const float* __restrict__ r, const float* __restrict__ k,
    const float* __restrict__ v, const float* __restrict__ d,
    const float* __restrict__ aw, const float* __restrict__ bw,
    const float* __restrict__ s0, float* __restrict__ o)
{
    const int bh = blockIdx.x;            // 0..63
    const int b = bh >> 5, hh = bh & 31;
    const int tid = threadIdx.x;
    const int vr = tid >> 1;
    const int koff = (tid & 1) * 32;
    const int n = tid & 63;

    float S[32];
    {
        const float* sp = s0 + ((size_t)bh*64 + vr)*64 + koff;
#pragma unroll
        for (int i=0;i<32;i++) S[i] = sp[i];
    }

    __shared__ float sh[2][6][64];        // 0=r 1=k 2=v 3=d 4=aw 5=bw
    const size_t rowbase = (size_t)b*TT*CC + hh*64;

    float p0, p1, p2;
    // t = 0 direct into smem
    {
        size_t idx = rowbase + n;
        if (tid < 64) { sh[0][0][n]=r[idx]; sh[0][1][n]=k[idx]; sh[0][2][n]=v[idx]; }
        else          { sh[0][3][n]=d[idx]; sh[0][4][n]=aw[idx]; sh[0][5][n]=bw[idx]; }
    }
    // t = 1 into regs
    {
        size_t idx = rowbase + (size_t)1*CC + n;
        if (tid < 64) { p0=r[idx]; p1=k[idx]; p2=v[idx]; }
        else          { p0=d[idx]; p1=aw[idx]; p2=bw[idx]; }
    }
    __syncthreads();

    for (int t = 0; t < TT; t++) {
        const int buf = t & 1;
        if (t+1 < TT) {
            if (tid < 64) { sh[buf^1][0][n]=p0; sh[buf^1][1][n]=p1; sh[buf^1][2][n]=p2; }
            else          { sh[buf^1][3][n]=p0; sh[buf^1][4][n]=p1; sh[buf^1][5][n]=p2; }
        }
        if (t+2 < TT) {
            size_t idx = rowbase + (size_t)(t+2)*CC + n;
            if (tid < 64) { p0=r[idx]; p1=k[idx]; p2=v[idx]; }
            else          { p0=d[idx]; p1=aw[idx]; p2=bw[idx]; }
        }

        const float* shr = sh[buf][0];
        const float* shk = sh[buf][1];
        const float* shv = sh[buf][2];
        const float* shd = sh[buf][3];
        const float* sha = sh[buf][4];
        const float* shb = sh[buf][5];

        float sa0=0.f, sa1=0.f, sa2=0.f, sa3=0.f;
#pragma unroll
        for (int i=0;i<32;i+=4){
            float4 a4 = *(const float4*)&sha[koff+i];
            sa0 += S[i+0]*a4.x; sa1 += S[i+1]*a4.y;
            sa2 += S[i+2]*a4.z; sa3 += S[i+3]*a4.w;
        }
        float sa = (sa0+sa1)+(sa2+sa3);
        sa += __shfl_xor_sync(0xffffffffu, sa, 1);

        const float vt = shv[vr];
        float o0=0.f,o1=0.f,o2=0.f,o3=0.f;
#pragma unroll
        for (int i=0;i<32;i+=4){
            float4 d4 = *(const float4*)&shd[koff+i];
            float4 b4 = *(const float4*)&shb[koff+i];
            float4 k4 = *(const float4*)&shk[koff+i];
            float4 r4 = *(const float4*)&shr[koff+i];
            S[i+0] = S[i+0]*d4.x + sa*b4.x + vt*k4.x;
            S[i+1] = S[i+1]*d4.y + sa*b4.y + vt*k4.y;
            S[i+2] = S[i+2]*d4.z + sa*b4.z + vt*k4.z;
            S[i+3] = S[i+3]*d4.w + sa*b4.w + vt*k4.w;
            o0 += S[i+0]*r4.x; o1 += S[i+1]*r4.y;
            o2 += S[i+2]*r4.z; o3 += S[i+3]*r4.w;
        }
        float oo = (o0+o1)+(o2+o3);
        oo += __shfl_xor_sync(0xffffffffu, oo, 1);
        if ((tid & 1)==0) o[rowbase + (size_t)t*CC + vr] = oo;
        __syncthreads();
    }
}

// ---------------------------------------------------------------------------
// K7: group norm + per-head bonus + gate multiply
// ---------------------------------------------------------------------------
__global__ __launch_bounds__(256) void gn_kernel(
    const float* __restrict__ o, const float* __restrict__ r,
    const float* __restrict__ kf, const float* __restrict__ vf,
    const float* __restrict__ gg, const float* __restrict__ rk,
    const float* __restrict__ gnw, const float* __restrict__ gnb,
    float* __restrict__ xo)
{
    const int tid = threadIdx.x;
    const int g = tid >> 6, n = tid & 63;
    const size_t head = (size_t)blockIdx.x*4 + g;
    const int h = (int)(head & (HH-1));
    const size_t idx = head*64 + n;
    const int c = h*64 + n;

    float ov = o[idx];
    float rv = r[idx], kv = kf[idx];
    float s1 = ov, s2 = ov*ov, s3 = rv*kv*rk[c];
#pragma unroll
    for (int off=16; off; off>>=1){
        s1 += __shfl_xor_sync(0xffffffffu, s1, off);
        s2 += __shfl_xor_sync(0xffffffffu, s2, off);
        s3 += __shfl_xor_sync(0xffffffffu, s3, off);
    }
    __shared__ float red[8][3];
    if ((tid & 31)==0){ int w = tid>>5; red[w][0]=s1; red[w][1]=s2; red[w][2]=s3; }
    __syncthreads();
    float S1 = red[g*2][0]+red[g*2+1][0];
    float S2 = red[g*2][1]+red[g*2+1][1];
    float S3 = red[g*2][2]+red[g*2+1][2];
    float mu = S1*(1.f/64.f);
    float var = S2*(1.f/64.f) - mu*mu;
    float y = (ov-mu)*rsqrtf(var + 6.4e-4f)*gnw[c] + gnb[c] + S3*vf[idx];
    xo[idx] = y * gg[idx];
}

// ---------------------------------------------------------------------------
// Launch
// ---------------------------------------------------------------------------
extern "C" void kernel_launch(void* const* d_in, const int* in_sizes, int n_in,
                              void* d_out, int out_size)
{
    const float* h      = (const float*)d_in[0];
    const float* shift  = (const float*)d_in[1];
    const float* s0     = (const float*)d_in[2];
    const float* vfirst = (const float*)d_in[3];
    const float* x_r = (const float*)d_in[4];
    const float* x_w = (const float*)d_in[5];
    const float* x_k = (const float*)d_in[6];
    const float* x_v = (const float*)d_in[7];
    const float* x_a = (const float*)d_in[8];
    const float* x_g = (const float*)d_in[9];
    const float* w0 = (const float*)d_in[10];
    const float* w1 = (const float*)d_in[11];
    const float* w2 = (const float*)d_in[12];
    const float* a0 = (const float*)d_in[13];
    const float* a1 = (const float*)d_in[14];
    const float* a2 = (const float*)d_in[15];
    const float* v0 = (const float*)d_in[16];
    const float* v1 = (const float*)d_in[17];
    const float* v2 = (const float*)d_in[18];
    const float* g1 = (const float*)d_in[19];
    const float* g2 = (const float*)d_in[20];
    const float* k_k = (const float*)d_in[21];
    const float* k_a = (const float*)d_in[22];
    const float* r_k = (const float*)d_in[23];
    const float* W_r = (const float*)d_in[24];
    const float* W_k = (const float*)d_in[25];
    const float* W_v = (const float*)d_in[26];
    const float* W_o = (const float*)d_in[27];
    const float* gnw = (const float*)d_in[28];
    const float* gnb = (const float*)d_in[29];
    float* out = (float*)d_out;

    float* S = nullptr;
    cudaGetSymbolAddress((void**)&S, g_scratch);

    float* xr = S + (size_t)S_XR*BTC;   float* xw = S + (size_t)S_XW*BTC;
    float* xk = S + (size_t)S_XK*BTC;   float* xv = S + (size_t)S_XV*BTC;
    float* xa = S + (size_t)S_XA*BTC;   float* xg = S + (size_t)S_XG*BTC;
    float* rb = S + (size_t)S_R*BTC;    float* kb = S + (size_t)S_K*BTC;
    float* vb = S + (size_t)S_V*BTC;
    float* decay = S + (size_t)S_DECAY*BTC;
    float* asig  = S + (size_t)S_ASIG*BTC;
    float* gbuf  = S + (size_t)S_G*BTC;
    float* awb = S + (size_t)S_AW*BTC;  float* bwb = S + (size_t)S_BW*BTC;
    float* kfb = S + (size_t)S_KF*BTC;  float* vfb = S + (size_t)S_VF*BTC;
    float* ob  = S + (size_t)S_O*BTC;   float* xob = S + (size_t)S_XO*BTC;
    float* Uw = S + U_W_OFF;  float* Ua = S + U_A_OFF;
    float* Uv = S + U_V_OFF;  float* Ug = S + U_G_OFF;

    // 1. token shift + mixes
    mix_kernel<<<4096, 256>>>(h, shift, x_r, x_w, x_k, x_v, x_a, x_g,
                              xr, xw, xk, xv, xa, xg);

    // 2. big projections
    dim3 gg(16,16);
    gemm_nt_2048<<<gg, 256>>>(xr, W_r, rb);
    gemm_nt_2048<<<gg, 256>>>(xk, W_k, kb);
    gemm_nt_2048<<<gg, 256>>>(xv, W_v, vb);

    // 3. LoRA stage 1
    lora1_kernel<64, 1><<<128, 256>>>(xw, w1, Uw);   // tanh
    lora1_kernel<64, 0><<<128, 256>>>(xa, a1, Ua);
    lora1_kernel<32, 0><<<128, 256>>>(xv, v1, Uv);
    lora1_kernel<128,2><<<128, 256>>>(xg, g1, Ug);   // sigmoid

    // 4. LoRA stage 2 + epilogues
    dim3 g2d(8, 64);
    stage2_kernel<64, 0><<<g2d, 256>>>(Uw, w2, w0, decay, nullptr, nullptr);
    stage2_kernel<64, 1><<<g2d, 256>>>(Ua, a2, a0, asig, nullptr, nullptr);
    stage2_kernel<32, 2><<<g2d, 256>>>(Uv, v2, v0, vfb, vb, vfirst);
    stage2_kernel<128,3><<<g2d, 256>>>(Ug, g2, nullptr, gbuf, nullptr, nullptr);

    // 5. kk-normalize / k lerp prep
    prep_kernel<<<BT*HH/4, 256>>>(kb, asig, k_k, k_a, awb, bwb, kfb);

    // 6. WKV7 recurrence
    wkv_kernel<<<BB*HH, 128>>>(rb, kfb, vfb, decay, awb, bwb, s0, ob);

    // 7. group norm + bonus + gate
    gn_kernel<<<BT*HH/4, 256>>>(ob, rb, kfb, vfb, gbuf, r_k, gnw, gnb, xob);

    // 8. output projection
    gemm_nt_2048<<<gg, 256>>>(xob, W_o, out);
}

// round 4
// speedup vs baseline: 1.4383x; 1.4383x over previous
#include <cuda_runtime.h>
#include <cuda_bf16.h>
#include <math.h>
#include <cstdint>

// Problem constants
#define BB 2
#define TT 1024
#define CC 2048
#define HH 32
#define NN 64
#define BT (BB*TT)              // 2048
#define BTC (BB*TT*CC)          // 4194304  (== CC*CC)

// ---------------------------------------------------------------------------
// Scratch (static device memory)
// ---------------------------------------------------------------------------
enum { S_XW=0, S_XA, S_XV, S_XG, S_R, S_K, S_V,
       S_DECAY, S_ASIG, S_G, S_AW, S_BW, S_KF, S_VF, S_O, N_F32 };
enum { B_XRH=0, B_XRL, B_XKH, B_XKL, B_XVH, B_XVL, B_XOH, B_XOL,
       B_WRH, B_WRL, B_WKH, B_WKL, B_WVH, B_WVL, B_WOH, B_WOL, N_BF16 };
#define BF16_BASE ((size_t)N_F32*BTC)                 // in floats
#define U_W_OFF   (BF16_BASE + (size_t)N_BF16*BTC/2)
#define U_A_OFF   (U_W_OFF + (size_t)BT*64)
#define U_V_OFF   (U_A_OFF + (size_t)BT*64)
#define U_G_OFF   (U_V_OFF + (size_t)BT*32)
#define SCRATCH_FLOATS (U_G_OFF + (size_t)BT*128)

__device__ float g_scratch[SCRATCH_FLOATS];

// ---------------------------------------------------------------------------
// PTX helpers (plain sm_103-compatible: ldmatrix / mma.sync / cp.async only)
// ---------------------------------------------------------------------------
__device__ __forceinline__ uint32_t smem_u32(const void* p) {
    uint32_t a;
    asm("{ .reg .u64 t; cvta.to.shared.u64 t, %1; cvt.u32.u64 %0, t; }" : "=r"(a) : "l"(p));
    return a;
}
#define CP16(dst, src) \
    asm volatile("cp.async.cg.shared.global [%0], [%1], 16;" :: "r"(dst), "l"(src))
#define CP_COMMIT() asm volatile("cp.async.commit_group;" ::: "memory")
#define CP_WAIT2()  asm volatile("cp.async.wait_group 2;"  ::: "memory")
#define LDSM4(r, addr) \
    asm volatile("ldmatrix.sync.aligned.m8n8.x4.shared.b16 {%0,%1,%2,%3}, [%4];" \
        : "=r"((r)[0]), "=r"((r)[1]), "=r"((r)[2]), "=r"((r)[3]) : "r"(addr))
#define MMA16816(d, a, b0, b1) \
    asm volatile("mma.sync.aligned.m16n8k16.row.col.f32.bf16.bf16.f32 " \
        "{%0,%1,%2,%3}, {%4,%5,%6,%7}, {%8,%9}, {%0,%1,%2,%3};" \
        : "+f"((d)[0]), "+f"((d)[1]), "+f"((d)[2]), "+f"((d)[3]) \
        : "r"((a)[0]), "r"((a)[1]), "r"((a)[2]), "r"((a)[3]), "r"(b0), "r"(b1))

// ---------------------------------------------------------------------------
// hi/lo split helpers
// ---------------------------------------------------------------------------
__device__ __forceinline__ void split_hilo(float v, __nv_bfloat16& h, __nv_bfloat16& l) {
    h = __float2bfloat16(v);
    l = __float2bfloat16(v - __bfloat162float(h));
}
__device__ __forceinline__ void store_hilo4(__nv_bfloat16* hi, __nv_bfloat16* lo,
                                            size_t off, float4 v) {
    __nv_bfloat16 hv[4], lv[4];
    split_hilo(v.x, hv[0], lv[0]); split_hilo(v.y, hv[1], lv[1]);
    split_hilo(v.z, hv[2], lv[2]); split_hilo(v.w, hv[3], lv[3]);
    *(uint2*)&hi[off] = *(uint2*)hv;
    *(uint2*)&lo[off] = *(uint2*)lv;
}

// ---------------------------------------------------------------------------
// K0: fp32 -> bf16 hi/lo conversion (weights)
// ---------------------------------------------------------------------------
__global__ __launch_bounds__(256) void cvt_hilo_kernel(
    const float* __restrict__ x, __nv_bfloat16* __restrict__ hi,
    __nv_bfloat16* __restrict__ lo)
{
    size_t i = ((size_t)blockIdx.x * 256 + threadIdx.x) * 4;
    float4 v = *(const float4*)&x[i];
    store_hilo4(hi, lo, i, v);
}

// ---------------------------------------------------------------------------
// K1: token shift + 6-way mix
// ---------------------------------------------------------------------------
__global__ __launch_bounds__(256) void mix_kernel(
    const float* __restrict__ h, const float* __restrict__ shift,
    const float* __restrict__ mr, const float* __restrict__ mw,
    const float* __restrict__ mk, const float* __restrict__ mv,
    const float* __restrict__ ma, const float* __restrict__ mg,
    __nv_bfloat16* __restrict__ xrh, __nv_bfloat16* __restrict__ xrl,
    float* __restrict__ oxw,
    __nv_bfloat16* __restrict__ xkh, __nv_bfloat16* __restrict__ xkl,
    float* __restrict__ oxv,
    __nv_bfloat16* __restrict__ xvh, __nv_bfloat16* __restrict__ xvl,
    float* __restrict__ oxa, float* __restrict__ oxg)
{
    int gid = blockIdx.x * 256 + threadIdx.x;
    int row = gid >> 9;
    int c   = (gid & 511) << 2;
    int t   = row & (TT-1);
    int b   = row >> 10;
    size_t off = (size_t)row * CC + c;

    float4 hv = *(const float4*)&h[off];
    float4 pv;
    if (t == 0) pv = *(const float4*)&shift[(size_t)b*CC + c];
    else        pv = *(const float4*)&h[off - CC];
    float4 xx = make_float4(pv.x-hv.x, pv.y-hv.y, pv.z-hv.z, pv.w-hv.w);

#define MIXV(mvec, o)                                                 \
    {   float4 m = *(const float4*)&mvec[c];                          \
        o = make_float4(hv.x + xx.x*m.x, hv.y + xx.y*m.y,             \
                        hv.z + xx.z*m.z, hv.w + xx.w*m.w); }
    float4 vr; MIXV(mr, vr); store_hilo4(xrh, xrl, off, vr);
    float4 vw; MIXV(mw, vw); *(float4*)&oxw[off] = vw;
    float4 vk; MIXV(mk, vk); store_hilo4(xkh, xkl, off, vk);
    float4 vv; MIXV(mv, vv); *(float4*)&oxv[off] = vv; store_hilo4(xvh, xvl, off, vv);
    float4 va; MIXV(ma, va); *(float4*)&oxa[off] = va;
    float4 vg; MIXV(mg, vg); *(float4*)&oxg[off] = vg;
#undef MIXV
}

// ---------------------------------------------------------------------------
// K2: HMMA bf16x3 GEMM  Y[2048,2048] = (Ahi+Alo) @ (Bhi+Blo)^T   (fp32 out)
//     CTA tile 128x256, warp tile 64x64, BK=32, 3-stage cp.async pipeline.
//     smem tile layout: 64B rows, xor-swizzled 16B chunks (conflict-free).
// ---------------------------------------------------------------------------
#define GSTAGES 3
#define TILE_A 8192              // 128 rows x 64 B
#define TILE_B 16384             // 256 rows x 64 B
#define STAGE_B (2*TILE_A + 2*TILE_B)   // 49152
#define GEMM_SMEM (GSTAGES*STAGE_B)     // 147456

__device__ __forceinline__ uint32_t swz(uint32_t row, uint32_t chunk) {
    return row*64u + ((chunk ^ ((row >> 1) & 3u)) << 4);
}

__global__ __launch_bounds__(256, 1) void gemm_bf16x3(
    const __nv_bfloat16* __restrict__ Ahi, const __nv_bfloat16* __restrict__ Alo,
    const __nv_bfloat16* __restrict__ Bhi, const __nv_bfloat16* __restrict__ Blo,
    float* __restrict__ Y)
{
    extern __shared__ char dynsmem[];
    const uint32_t sb = smem_u32(dynsmem);
    const int tid  = threadIdx.x;
    const int lane = tid & 31;
    const int warp = tid >> 5;
    const int wm = warp >> 2;            // 0..1
    const int wn = warp & 3;             // 0..3
    const int bm = blockIdx.y << 7;      // 128-row tile
    const int bn = blockIdx.x << 8;      // 256-col tile

    auto load_stage = [&](int chunk, int stage) {
        const uint32_t st = sb + (uint32_t)stage * STAGE_B;
        const int k0 = chunk << 5;
#pragma unroll
        for (int i = 0; i < 2; i++) {                 // A tiles: 512 x 16B each
            int idx = tid + (i << 8);
            int row = idx >> 2, ch = idx & 3;
            uint32_t d = st + swz(row, ch);
            size_t g = (size_t)(bm + row) * CC + k0 + ch * 8;
            CP16(d,          Ahi + g);
            CP16(d + TILE_A, Alo + g);
        }
#pragma unroll
        for (int i = 0; i < 4; i++) {                 // B tiles: 1024 x 16B each
            int idx = tid + (i << 8);
            int row = idx >> 2, ch = idx & 3;
            uint32_t d = st + 2*TILE_A + swz(row, ch);
            size_t g = (size_t)(bn + row) * CC + k0 + ch * 8;
            CP16(d,          Bhi + g);
            CP16(d + TILE_B, Blo + g);
        }
    };

    float acc[4][8][4];
#pragma unroll
    for (int mi=0;mi<4;mi++)
#pragma unroll
        for (int ni=0;ni<8;ni++)
#pragma unroll
            for (int j=0;j<4;j++) acc[mi][ni][j] = 0.f;

#pragma unroll
    for (int s = 0; s < GSTAGES; s++) { load_stage(s, s); CP_COMMIT(); }

    // precomputed ldmatrix row/chunk components
    const int a_row = wm*64 + (lane & 7) + ((lane >> 3) & 1) * 8;  // + mi*16
    const int a_ch  = (lane >> 4);                                  // + ks*2
    const int b_row = wn*64 + (lane & 7) + (lane >> 4) * 8;         // + j*16
    const int b_ch  = ((lane >> 3) & 1);                            // + ks*2

    for (int it = 0; it < 64; it++) {
        const int stage = it % GSTAGES;
        const uint32_t st = sb + (uint32_t)stage * STAGE_B;
        CP_WAIT2();
        __syncthreads();

#pragma unroll
        for (int ks = 0; ks < 2; ks++) {
            uint32_t ah[4][4], al[4][4], b[4][4];
#pragma unroll
            for (int mi = 0; mi < 4; mi++) {
                uint32_t a = st + swz((uint32_t)(a_row + mi*16), (uint32_t)(a_ch + ks*2));
                LDSM4(ah[mi], a);
                LDSM4(al[mi], a + TILE_A);
            }
#pragma unroll
            for (int j = 0; j < 4; j++) {
                uint32_t baddr = st + 2*TILE_A +
                    swz((uint32_t)(b_row + j*16), (uint32_t)(b_ch + ks*2));
                LDSM4(b[j], baddr);
            }
#pragma unroll
            for (int mi = 0; mi < 4; mi++)
#pragma unroll
                for (int ni = 0; ni < 8; ni++)
                    MMA16816(acc[mi][ni], ah[mi], b[ni>>1][(ni&1)*2], b[ni>>1][(ni&1)*2+1]);
#pragma unroll
            for (int mi = 0; mi < 4; mi++)
#pragma unroll
                for (int ni = 0; ni < 8; ni++)
                    MMA16816(acc[mi][ni], al[mi], b[ni>>1][(ni&1)*2], b[ni>>1][(ni&1)*2+1]);
#pragma unroll
            for (int j = 0; j < 4; j++) {
                uint32_t baddr = st + 2*TILE_A + TILE_B +
                    swz((uint32_t)(b_row + j*16), (uint32_t)(b_ch + ks*2));
                LDSM4(b[j], baddr);
            }
#pragma unroll
            for (int mi = 0; mi < 4; mi++)
#pragma unroll
                for (int ni = 0; ni < 8; ni++)
                    MMA16816(acc[mi][ni], ah[mi], b[ni>>1][(ni&1)*2], b[ni>>1][(ni&1)*2+1]);
        }

        __syncthreads();
        if (it + GSTAGES < 64) load_stage(it + GSTAGES, stage);
        CP_COMMIT();
    }

    // epilogue: write fp32
    const int erow = bm + wm*64 + (lane >> 2);
    const int ecol = bn + wn*64 + (lane & 3) * 2;
#pragma unroll
    for (int mi = 0; mi < 4; mi++)
#pragma unroll
        for (int ni = 0; ni < 8; ni++) {
            size_t r0 = (size_t)(erow + mi*16) * CC + ecol + ni*8;
            *(float2*)&Y[r0]        = make_float2(acc[mi][ni][0], acc[mi][ni][1]);
            *(float2*)&Y[r0 + 8*CC] = make_float2(acc[mi][ni][2], acc[mi][ni][3]);
        }
}

// ---------------------------------------------------------------------------
// K3: LoRA stage 1: U[BT,D] = act( X[BT,2048] @ G[2048,D] )
// ---------------------------------------------------------------------------
template<int D, int ACT>
__global__ __launch_bounds__(256) void lora1_kernel(
    const float* __restrict__ X, const float* __restrict__ G,
    float* __restrict__ U)
{
    constexpr int BM = 16, BK = 32;
    constexpr int STEP = 256 / D;
    constexpr int NR = BM / STEP;
    constexpr int NG = (BK*D) / (4*256);
    __shared__ float Xs[BK][BM+1];
    __shared__ float Gs[BK][D];

    const int tid = threadIdx.x;
    const int bm = blockIdx.x * BM;
    const int c = tid % D;
    const int rg = tid / D;

    float acc[NR];
#pragma unroll
    for (int i=0;i<NR;i++) acc[i]=0.f;

    for (int k0 = 0; k0 < 2048; k0 += BK) {
        if (tid < 128) {
            int row = tid >> 3, cc = (tid & 7) << 2;
            float4 xv = *(const float4*)&X[(size_t)(bm+row)*CC + k0 + cc];
            Xs[cc+0][row]=xv.x; Xs[cc+1][row]=xv.y;
            Xs[cc+2][row]=xv.z; Xs[cc+3][row]=xv.w;
        }
#pragma unroll
        for (int i=0;i<NG;i++){
            int lin = tid + (i<<8);
            int kr = lin / (D/4);
            int cc = (lin % (D/4)) << 2;
            *(float4*)&Gs[kr][cc] = *(const float4*)&G[(size_t)(k0+kr)*D + cc];
        }
        __syncthreads();
#pragma unroll
        for (int kk=0;kk<BK;kk++){
            float gv = Gs[kk][c];
#pragma unroll
            for (int i=0;i<NR;i++)
                acc[i] += Xs[kk][rg + i*STEP] * gv;
        }
        __syncthreads();
    }
#pragma unroll
    for (int i=0;i<NR;i++){
        float y = acc[i];
        if (ACT==1) y = tanhf(y);
        else if (ACT==2) y = 1.f/(1.f+expf(-y));
        U[(size_t)(bm + rg + i*STEP)*D + c] = y;
    }
}

// ---------------------------------------------------------------------------
// K4: LoRA stage 2 + epilogue
// ---------------------------------------------------------------------------
template<int D, int MODE>
__global__ __launch_bounds__(256) void stage2_kernel(
    const float* __restrict__ U, const float* __restrict__ V2,
    const float* __restrict__ bias, float* __restrict__ out,
    const float* __restrict__ e1, const float* __restrict__ e2)
{
    constexpr int ROWS = 32;
    constexpr int NL = (ROWS*D)/(4*256);
    __shared__ float Us[ROWS][D];
    const int tid = threadIdx.x;
    const int row0 = blockIdx.y * ROWS;
    const int c = blockIdx.x * 256 + tid;

#pragma unroll
    for (int i=0;i<NL;i++){
        int lin = tid + (i<<8);
        int rr = lin / (D/4), cc = (lin % (D/4)) << 2;
        *(float4*)&Us[rr][cc] = *(const float4*)&U[(size_t)(row0+rr)*D + cc];
    }
    __syncthreads();

    float acc[ROWS];
#pragma unroll
    for (int r=0;r<ROWS;r++) acc[r]=0.f;

#pragma unroll
    for (int d0=0; d0<D; d0+=4){
        float v0 = V2[(size_t)(d0+0)*CC + c];
        float v1 = V2[(size_t)(d0+1)*CC + c];
        float v2 = V2[(size_t)(d0+2)*CC + c];
        float v3 = V2[(size_t)(d0+3)*CC + c];
#pragma unroll
        for (int r=0;r<ROWS;r++){
            float4 u = *(const float4*)&Us[r][d0];
            acc[r] += u.x*v0 + u.y*v1 + u.z*v2 + u.w*v3;
        }
    }
    float bv = (MODE==3) ? 0.f : bias[c];
#pragma unroll
    for (int r=0;r<ROWS;r++){
        size_t idx = (size_t)(row0+r)*CC + c;
        float y = acc[r] + bv;
        if (MODE==0)      out[idx] = 0.6065306597126334f * (1.f/(1.f+expf(-y)));
        else if (MODE==1) out[idx] = 1.f/(1.f+expf(-y));
        else if (MODE==2) {
            float s = 1.f/(1.f+expf(-y));
            float vr = e1[idx];
            out[idx] = vr + (e2[idx]-vr)*s;
        } else            out[idx] = y;
    }
}

// ---------------------------------------------------------------------------
// K5: per-(b,t,h) prep
// ---------------------------------------------------------------------------
__global__ __launch_bounds__(256) void prep_kernel(
    const float* __restrict__ k, const float* __restrict__ asig,
    const float* __restrict__ kkvec, const float* __restrict__ kavec,
    float* __restrict__ aw, float* __restrict__ bw, float* __restrict__ kf)
{
    const int tid = threadIdx.x;
    const int g = tid >> 6, n = tid & 63;
    const size_t head = (size_t)blockIdx.x*4 + g;
    const size_t idx = head*64 + n;
    const int c = (int)(idx & (CC-1));

    float kv = k[idx];
    float kk = kv * kkvec[c];
    float ss = kk*kk;
#pragma unroll
    for (int off=16; off; off>>=1) ss += __shfl_xor_sync(0xffffffffu, ss, off);
    __shared__ float red[8];
    if ((tid & 31)==0) red[tid>>5] = ss;
    __syncthreads();
    float tot = red[g*2] + red[g*2+1];
    float inv = 1.f / fmaxf(sqrtf(tot), 1e-12f);
    float kkn = kk * inv;
    float a = asig[idx];
    aw[idx] = -kkn;
    bw[idx] = kkn * a;
    kf[idx] = kv + kavec[c]*(kv*a - kv);
}

// ---------------------------------------------------------------------------
// K6: WKV7 recurrence
// ---------------------------------------------------------------------------
__global__ __launch_bounds__(128) void wkv_kernel(
    const float* __restrict__ r, const float* __restrict__ k,
    const float* __restrict__ v, const float* __restrict__ d,
    const float* __restrict__ aw, const float* __restrict__ bw,
    const float* __restrict__ s0, float* __restrict__ o)
{
    const int bh = blockIdx.x;
    const int b = bh >> 5, hh = bh & 31;
    const int tid = threadIdx.x;
    const int vr = tid >> 1;
    const int koff = (tid & 1) * 32;
    const int n = tid & 63;

    float S[32];
    {
        const float* sp = s0 + ((size_t)bh*64 + vr)*64 + koff;
#pragma unroll
        for (int i=0;i<32;i++) S[i] = sp[i];
    }

    __shared__ float sh[2][6][64];
    const size_t rowbase = (size_t)b*TT*CC + hh*64;

    float p0, p1, p2;
    {
        size_t idx = rowbase + n;
        if (tid < 64) { sh[0][0][n]=r[idx]; sh[0][1][n]=k[idx]; sh[0][2][n]=v[idx]; }
        else          { sh[0][3][n]=d[idx]; sh[0][4][n]=aw[idx]; sh[0][5][n]=bw[idx]; }
    }
    {
        size_t idx = rowbase + (size_t)1*CC + n;
        if (tid < 64) { p0=r[idx]; p1=k[idx]; p2=v[idx]; }
        else          { p0=d[idx]; p1=aw[idx]; p2=bw[idx]; }
    }
    __syncthreads();

    for (int t = 0; t < TT; t++) {
        const int buf = t & 1;
        if (t+1 < TT) {
            if (tid < 64) { sh[buf^1][0][n]=p0; sh[buf^1][1][n]=p1; sh[buf^1][2][n]=p2; }
            else          { sh[buf^1][3][n]=p0; sh[buf^1][4][n]=p1; sh[buf^1][5][n]=p2; }
        }
        if (t+2 < TT) {
            size_t idx = rowbase + (size_t)(t+2)*CC + n;
            if (tid < 64) { p0=r[idx]; p1=k[idx]; p2=v[idx]; }
            else          { p0=d[idx]; p1=aw[idx]; p2=bw[idx]; }
        }

        const float* shr = sh[buf][0];
        const float* shk = sh[buf][1];
        const float* shv = sh[buf][2];
        const float* shd = sh[buf][3];
        const float* sha = sh[buf][4];
        const float* shb = sh[buf][5];

        float sa0=0.f, sa1=0.f, sa2=0.f, sa3=0.f;
#pragma unroll
        for (int i=0;i<32;i+=4){
            float4 a4 = *(const float4*)&sha[koff+i];
            sa0 += S[i+0]*a4.x; sa1 += S[i+1]*a4.y;
            sa2 += S[i+2]*a4.z; sa3 += S[i+3]*a4.w;
        }
        float sa = (sa0+sa1)+(sa2+sa3);
        sa += __shfl_xor_sync(0xffffffffu, sa, 1);

        const float vt = shv[vr];
        float o0=0.f,o1=0.f,o2=0.f,o3=0.f;
#pragma unroll
        for (int i=0;i<32;i+=4){
            float4 d4 = *(const float4*)&shd[koff+i];
            float4 b4 = *(const float4*)&shb[koff+i];
            float4 k4 = *(const float4*)&shk[koff+i];
            float4 r4 = *(const float4*)&shr[koff+i];
            S[i+0] = S[i+0]*d4.x + sa*b4.x + vt*k4.x;
            S[i+1] = S[i+1]*d4.y + sa*b4.y + vt*k4.y;
            S[i+2] = S[i+2]*d4.z + sa*b4.z + vt*k4.z;
            S[i+3] = S[i+3]*d4.w + sa*b4.w + vt*k4.w;
            o0 += S[i+0]*r4.x; o1 += S[i+1]*r4.y;
            o2 += S[i+2]*r4.z; o3 += S[i+3]*r4.w;
        }
        float oo = (o0+o1)+(o2+o3);
        oo += __shfl_xor_sync(0xffffffffu, oo, 1);
        if ((tid & 1)==0) o[rowbase + (size_t)t*CC + vr] = oo;
        __syncthreads();
    }
}

// ---------------------------------------------------------------------------
// K7: group norm + per-head bonus + gate multiply -> bf16 hi/lo
// ---------------------------------------------------------------------------
__global__ __launch_bounds__(256) void gn_kernel(
    const float* __restrict__ o, const float* __restrict__ r,
    const float* __restrict__ kf, const float* __restrict__ vf,
    const float* __restrict__ gg, const float* __restrict__ rk,
    const float* __restrict__ gnw, const float* __restrict__ gnb,
    __nv_bfloat16* __restrict__ xoh, __nv_bfloat16* __restrict__ xol)
{
    const int tid = threadIdx.x;
    const int g = tid >> 6, n = tid & 63;
    const size_t head = (size_t)blockIdx.x*4 + g;
    const int h = (int)(head & (HH-1));
    const size_t idx = head*64 + n;
    const int c = h*64 + n;

    float ov = o[idx];
    float rv = r[idx], kv = kf[idx];
    float s1 = ov, s2 = ov*ov, s3 = rv*kv*rk[c];
#pragma unroll
    for (int off=16; off; off>>=1){
        s1 += __shfl_xor_sync(0xffffffffu, s1, off);
        s2 += __shfl_xor_sync(0xffffffffu, s2, off);
        s3 += __shfl_xor_sync(0xffffffffu, s3, off);
    }
    __shared__ float red[8][3];
    if ((tid & 31)==0){ int w = tid>>5; red[w][0]=s1; red[w][1]=s2; red[w][2]=s3; }
    __syncthreads();
    float S1 = red[g*2][0]+red[g*2+1][0];
    float S2 = red[g*2][1]+red[g*2+1][1];
    float S3 = red[g*2][2]+red[g*2+1][2];
    float mu = S1*(1.f/64.f);
    float var = S2*(1.f/64.f) - mu*mu;
    float y = (ov-mu)*rsqrtf(var + 6.4e-4f)*gnw[c] + gnb[c] + S3*vf[idx];
    float xo = y * gg[idx];
    __nv_bfloat16 hv, lv;
    split_hilo(xo, hv, lv);
    xoh[idx] = hv;
    xol[idx] = lv;
}

// ---------------------------------------------------------------------------
// Launch
// ---------------------------------------------------------------------------
extern "C" void kernel_launch(void* const* d_in, const int* in_sizes, int n_in,
                              void* d_out, int out_size)
{
    const float* h      = (const float*)d_in[0];
    const float* shift  = (const float*)d_in[1];
    const float* s0     = (const float*)d_in[2];
    const float* vfirst = (const float*)d_in[3];
    const float* x_r = (const float*)d_in[4];
    const float* x_w = (const float*)d_in[5];
    const float* x_k = (const float*)d_in[6];
    const float* x_v = (const float*)d_in[7];
    const float* x_a = (const float*)d_in[8];
    const float* x_g = (const float*)d_in[9];
    const float* w0 = (const float*)d_in[10];
    const float* w1 = (const float*)d_in[11];
    const float* w2 = (const float*)d_in[12];
    const float* a0 = (const float*)d_in[13];
    const float* a1 = (const float*)d_in[14];
    const float* a2 = (const float*)d_in[15];
    const float* v0 = (const float*)d_in[16];
    const float* v1 = (const float*)d_in[17];
    const float* v2 = (const float*)d_in[18];
    const float* g1 = (const float*)d_in[19];
    const float* g2 = (const float*)d_in[20];
    const float* k_k = (const float*)d_in[21];
    const float* k_a = (const float*)d_in[22];
    const float* r_k = (const float*)d_in[23];
    const float* W_r = (const float*)d_in[24];
    const float* W_k = (const float*)d_in[25];
    const float* W_v = (const float*)d_in[26];
    const float* W_o = (const float*)d_in[27];
    const float* gnw = (const float*)d_in[28];
    const float* gnb = (const float*)d_in[29];
    float* out = (float*)d_out;

    float* S = nullptr;
    cudaGetSymbolAddress((void**)&S, g_scratch);

    float* xw    = S + (size_t)S_XW*BTC;
    float* xa    = S + (size_t)S_XA*BTC;
    float* xv    = S + (size_t)S_XV*BTC;
    float* xg    = S + (size_t)S_XG*BTC;
    float* rb    = S + (size_t)S_R*BTC;
    float* kb    = S + (size_t)S_K*BTC;
    float* vb    = S + (size_t)S_V*BTC;
    float* decay = S + (size_t)S_DECAY*BTC;
    float* asig  = S + (size_t)S_ASIG*BTC;
    float* gbuf  = S + (size_t)S_G*BTC;
    float* awb   = S + (size_t)S_AW*BTC;
    float* bwb   = S + (size_t)S_BW*BTC;
    float* kfb   = S + (size_t)S_KF*BTC;
    float* vfb   = S + (size_t)S_VF*BTC;
    float* ob    = S + (size_t)S_O*BTC;

    __nv_bfloat16* bfb = (__nv_bfloat16*)(S + BF16_BASE);
#define BF(i) (bfb + (size_t)(i)*BTC)
    __nv_bfloat16 *xrh=BF(B_XRH), *xrl=BF(B_XRL), *xkh=BF(B_XKH), *xkl=BF(B_XKL);
    __nv_bfloat16 *xvh=BF(B_XVH), *xvl=BF(B_XVL), *xoh=BF(B_XOH), *xol=BF(B_XOL);
    __nv_bfloat16 *wrh=BF(B_WRH), *wrl=BF(B_WRL), *wkh=BF(B_WKH), *wkl=BF(B_WKL);
    __nv_bfloat16 *wvh=BF(B_WVH), *wvl=BF(B_WVL), *woh=BF(B_WOH), *wol=BF(B_WOL);
#undef BF
    float* Uw = S + U_W_OFF;  float* Ua = S + U_A_OFF;
    float* Uv = S + U_V_OFF;  float* Ug = S + U_G_OFF;

    cudaFuncSetAttribute(gemm_bf16x3,
                         cudaFuncAttributeMaxDynamicSharedMemorySize, GEMM_SMEM);

    // 0. weight conversions (fp32 -> bf16 hi/lo)
    cvt_hilo_kernel<<<BTC/1024, 256>>>(W_r, wrh, wrl);
    cvt_hilo_kernel<<<BTC/1024, 256>>>(W_k, wkh, wkl);
    cvt_hilo_kernel<<<BTC/1024, 256>>>(W_v, wvh, wvl);
    cvt_hilo_kernel<<<BTC/1024, 256>>>(W_o, woh, wol);

    // 1. token shift + mixes
    mix_kernel<<<4096, 256>>>(h, shift, x_r, x_w, x_k, x_v, x_a, x_g,
                              xrh, xrl, xw, xkh, xkl, xv, xvh, xvl, xa, xg);

    // 2. big projections on HMMA tensor cores (bf16x3)
    dim3 gg(8, 16);     // N tiles x M tiles
    gemm_bf16x3<<<gg, 256, GEMM_SMEM>>>(xrh, xrl, wrh, wrl, rb);
    gemm_bf16x3<<<gg, 256, GEMM_SMEM>>>(xkh, xkl, wkh, wkl, kb);
    gemm_bf16x3<<<gg, 256, GEMM_SMEM>>>(xvh, xvl, wvh, wvl, vb);

    // 3. LoRA stage 1
    lora1_kernel<64, 1><<<128, 256>>>(xw, w1, Uw);   // tanh
    lora1_kernel<64, 0><<<128, 256>>>(xa, a1, Ua);
    lora1_kernel<32, 0><<<128, 256>>>(xv, v1, Uv);
    lora1_kernel<128,2><<<128, 256>>>(xg, g1, Ug);   // sigmoid

    // 4. LoRA stage 2 + epilogues
    dim3 g2d(8, 64);
    stage2_kernel<64, 0><<<g2d, 256>>>(Uw, w2, w0, decay, nullptr, nullptr);
    stage2_kernel<64, 1><<<g2d, 256>>>(Ua, a2, a0, asig, nullptr, nullptr);
    stage2_kernel<32, 2><<<g2d, 256>>>(Uv, v2, v0, vfb, vb, vfirst);
    stage2_kernel<128,3><<<g2d, 256>>>(Ug, g2, nullptr, gbuf, nullptr, nullptr);

    // 5. kk-normalize / k lerp prep
    prep_kernel<<<BT*HH/4, 256>>>(kb, asig, k_k, k_a, awb, bwb, kfb);

    // 6. WKV7 recurrence
    wkv_kernel<<<BB*HH, 128>>>(rb, kfb, vfb, decay, awb, bwb, s0, ob);

    // 7. group norm + bonus + gate
    gn_kernel<<<BT*HH/4, 256>>>(ob, rb, kfb, vfb, gbuf, r_k, gnw, gnb, xoh, xol);

    // 8. output projection
    gemm_bf16x3<<<gg, 256, GEMM_SMEM>>>(xoh, xol, woh, wol, out);
}

// round 5
// speedup vs baseline: 1.6190x; 1.1256x over previous
#include <cuda_runtime.h>
#include <cuda_bf16.h>
#include <math.h>
#include <cstdint>

// Problem constants
#define BB 2
#define TT 1024
#define CC 2048
#define HH 32
#define NN 64
#define BT (BB*TT)              // 2048
#define BTC (BB*TT*CC)          // 4194304  (== CC*CC)

// ---------------------------------------------------------------------------
// Scratch (static device memory)
// ---------------------------------------------------------------------------
enum { S_XW=0, S_XA, S_XV, S_XG, S_R, S_K, S_V,
       S_DECAY, S_ASIG, S_G, S_AW, S_BW, S_KF, S_VF, S_O, N_F32 };
enum { B_XRH=0, B_XRL, B_XKH, B_XKL, B_XVH, B_XVL, B_XOH, B_XOL,
       B_WRH, B_WRL, B_WKH, B_WKL, B_WVH, B_WVL, B_WOH, B_WOL, N_BF16 };
#define BF16_BASE ((size_t)N_F32*BTC)                 // in floats
#define U_W_OFF   (BF16_BASE + (size_t)N_BF16*BTC/2)
#define U_A_OFF   (U_W_OFF + (size_t)BT*64)
#define U_V_OFF   (U_A_OFF + (size_t)BT*64)
#define U_G_OFF   (U_V_OFF + (size_t)BT*32)
#define SCRATCH_FLOATS (U_G_OFF + (size_t)BT*128)

__device__ float g_scratch[SCRATCH_FLOATS];

// ---------------------------------------------------------------------------
// PTX helpers (plain sm_103-compatible)
// ---------------------------------------------------------------------------
__device__ __forceinline__ uint32_t smem_u32(const void* p) {
    uint32_t a;
    asm("{ .reg .u64 t; cvta.to.shared.u64 t, %1; cvt.u32.u64 %0, t; }" : "=r"(a) : "l"(p));
    return a;
}
#define CP16(dst, src) \
    asm volatile("cp.async.cg.shared.global [%0], [%1], 16;" :: "r"(dst), "l"(src))
#define CP_COMMIT() asm volatile("cp.async.commit_group;" ::: "memory")
#define CP_WAIT2()  asm volatile("cp.async.wait_group 2;"  ::: "memory")
#define LDSM4(r, addr) \
    asm volatile("ldmatrix.sync.aligned.m8n8.x4.shared.b16 {%0,%1,%2,%3}, [%4];" \
        : "=r"((r)[0]), "=r"((r)[1]), "=r"((r)[2]), "=r"((r)[3]) : "r"(addr))
#define MMA16816(d, a, b0, b1) \
    asm volatile("mma.sync.aligned.m16n8k16.row.col.f32.bf16.bf16.f32 " \
        "{%0,%1,%2,%3}, {%4,%5,%6,%7}, {%8,%9}, {%0,%1,%2,%3};" \
        : "+f"((d)[0]), "+f"((d)[1]), "+f"((d)[2]), "+f"((d)[3]) \
        : "r"((a)[0]), "r"((a)[1]), "r"((a)[2]), "r"((a)[3]), "r"(b0), "r"(b1))

// ---------------------------------------------------------------------------
// hi/lo split helpers
// ---------------------------------------------------------------------------
__device__ __forceinline__ void split_hilo(float v, __nv_bfloat16& h, __nv_bfloat16& l) {
    h = __float2bfloat16(v);
    l = __float2bfloat16(v - __bfloat162float(h));
}
__device__ __forceinline__ void store_hilo4(__nv_bfloat16* hi, __nv_bfloat16* lo,
                                            size_t off, float4 v) {
    __nv_bfloat16 hv[4], lv[4];
    split_hilo(v.x, hv[0], lv[0]); split_hilo(v.y, hv[1], lv[1]);
    split_hilo(v.z, hv[2], lv[2]); split_hilo(v.w, hv[3], lv[3]);
    *(uint2*)&hi[off] = *(uint2*)hv;
    *(uint2*)&lo[off] = *(uint2*)lv;
}

// ---------------------------------------------------------------------------
// K0: batched fp32 -> bf16 hi/lo conversion (4 weights in one launch)
// ---------------------------------------------------------------------------
struct CvtJobs { const float* x[4]; __nv_bfloat16* hi[4]; __nv_bfloat16* lo[4]; };

__global__ __launch_bounds__(256) void cvt_all_kernel(CvtJobs jobs)
{
    const int z = blockIdx.y;
    size_t i = ((size_t)blockIdx.x * 256 + threadIdx.x) * 4;
    float4 v = *(const float4*)&jobs.x[z][i];
    store_hilo4(jobs.hi[z], jobs.lo[z], i, v);
}

// ---------------------------------------------------------------------------
// K1: token shift + 6-way mix
// ---------------------------------------------------------------------------
__global__ __launch_bounds__(256) void mix_kernel(
    const float* __restrict__ h, const float* __restrict__ shift,
    const float* __restrict__ mr, const float* __restrict__ mw,
    const float* __restrict__ mk, const float* __restrict__ mv,
    const float* __restrict__ ma, const float* __restrict__ mg,
    __nv_bfloat16* __restrict__ xrh, __nv_bfloat16* __restrict__ xrl,
    float* __restrict__ oxw,
    __nv_bfloat16* __restrict__ xkh, __nv_bfloat16* __restrict__ xkl,
    float* __restrict__ oxv,
    __nv_bfloat16* __restrict__ xvh, __nv_bfloat16* __restrict__ xvl,
    float* __restrict__ oxa, float* __restrict__ oxg)
{
    int gid = blockIdx.x * 256 + threadIdx.x;
    int row = gid >> 9;
    int c   = (gid & 511) << 2;
    int t   = row & (TT-1);
    int b   = row >> 10;
    size_t off = (size_t)row * CC + c;

    float4 hv = *(const float4*)&h[off];
    float4 pv;
    if (t == 0) pv = *(const float4*)&shift[(size_t)b*CC + c];
    else        pv = *(const float4*)&h[off - CC];
    float4 xx = make_float4(pv.x-hv.x, pv.y-hv.y, pv.z-hv.z, pv.w-hv.w);

#define MIXV(mvec, o)                                                 \
    {   float4 m = *(const float4*)&mvec[c];                          \
        o = make_float4(hv.x + xx.x*m.x, hv.y + xx.y*m.y,             \
                        hv.z + xx.z*m.z, hv.w + xx.w*m.w); }
    float4 vr; MIXV(mr, vr); store_hilo4(xrh, xrl, off, vr);
    float4 vw; MIXV(mw, vw); *(float4*)&oxw[off] = vw;
    float4 vk; MIXV(mk, vk); store_hilo4(xkh, xkl, off, vk);
    float4 vv; MIXV(mv, vv); *(float4*)&oxv[off] = vv; store_hilo4(xvh, xvl, off, vv);
    float4 va; MIXV(ma, va); *(float4*)&oxa[off] = va;
    float4 vg; MIXV(mg, vg); *(float4*)&oxg[off] = vg;
#undef MIXV
}

// ---------------------------------------------------------------------------
// K2: HMMA bf16x3 GEMM (batched over blockIdx.z jobs)
//     CTA tile 128x256, warp tile 64x64, BK=32, 3-stage cp.async pipeline.
// ---------------------------------------------------------------------------
#define GSTAGES 3
#define TILE_A 8192              // 128 rows x 64 B
#define TILE_B 16384             // 256 rows x 64 B
#define STAGE_B (2*TILE_A + 2*TILE_B)   // 49152
#define GEMM_SMEM (GSTAGES*STAGE_B)     // 147456

struct GemmJob  { const __nv_bfloat16 *Ah, *Al, *Bh, *Bl; float* Y; };
struct GemmJobs { GemmJob j[3]; };

__device__ __forceinline__ uint32_t swz(uint32_t row, uint32_t chunk) {
    return row*64u + ((chunk ^ ((row >> 1) & 3u)) << 4);
}

__global__ __launch_bounds__(256, 1) void gemm_bf16x3(GemmJobs jobs)
{
    extern __shared__ char dynsmem[];
    const GemmJob gj = jobs.j[blockIdx.z];
    const __nv_bfloat16* __restrict__ Ahi = gj.Ah;
    const __nv_bfloat16* __restrict__ Alo = gj.Al;
    const __nv_bfloat16* __restrict__ Bhi = gj.Bh;
    const __nv_bfloat16* __restrict__ Blo = gj.Bl;
    float* __restrict__ Y = gj.Y;

    const uint32_t sb = smem_u32(dynsmem);
    const int tid  = threadIdx.x;
    const int lane = tid & 31;
    const int warp = tid >> 5;
    const int wm = warp >> 2;            // 0..1
    const int wn = warp & 3;             // 0..3
    const int bm = blockIdx.y << 7;      // 128-row tile
    const int bn = blockIdx.x << 8;      // 256-col tile

    auto load_stage = [&](int chunk, int stage) {
        const uint32_t st = sb + (uint32_t)stage * STAGE_B;
        const int k0 = chunk << 5;
#pragma unroll
        for (int i = 0; i < 2; i++) {                 // A tiles
            int idx = tid + (i << 8);
            int row = idx >> 2, ch = idx & 3;
            uint32_t d = st + swz(row, ch);
            size_t g = (size_t)(bm + row) * CC + k0 + ch * 8;
            CP16(d,          Ahi + g);
            CP16(d + TILE_A, Alo + g);
        }
#pragma unroll
        for (int i = 0; i < 4; i++) {                 // B tiles
            int idx = tid + (i << 8);
            int row = idx >> 2, ch = idx & 3;
            uint32_t d = st + 2*TILE_A + swz(row, ch);
            size_t g = (size_t)(bn + row) * CC + k0 + ch * 8;
            CP16(d,          Bhi + g);
            CP16(d + TILE_B, Blo + g);
        }
    };

    float acc[4][8][4];
#pragma unroll
    for (int mi=0;mi<4;mi++)
#pragma unroll
        for (int ni=0;ni<8;ni++)
#pragma unroll
            for (int j=0;j<4;j++) acc[mi][ni][j] = 0.f;

#pragma unroll
    for (int s = 0; s < GSTAGES; s++) { load_stage(s, s); CP_COMMIT(); }

    const int a_row = wm*64 + (lane & 7) + ((lane >> 3) & 1) * 8;
    const int a_ch  = (lane >> 4);
    const int b_row = wn*64 + (lane & 7) + (lane >> 4) * 8;
    const int b_ch  = ((lane >> 3) & 1);

    for (int it = 0; it < 64; it++) {
        const int stage = it % GSTAGES;
        const uint32_t st = sb + (uint32_t)stage * STAGE_B;
        CP_WAIT2();
        __syncthreads();

#pragma unroll
        for (int ks = 0; ks < 2; ks++) {
            uint32_t ah[4][4], al[4][4], b[4][4];
#pragma unroll
            for (int mi = 0; mi < 4; mi++) {
                uint32_t a = st + swz((uint32_t)(a_row + mi*16), (uint32_t)(a_ch + ks*2));
                LDSM4(ah[mi], a);
                LDSM4(al[mi], a + TILE_A);
            }
#pragma unroll
            for (int j = 0; j < 4; j++) {
                uint32_t baddr = st + 2*TILE_A +
                    swz((uint32_t)(b_row + j*16), (uint32_t)(b_ch + ks*2));
                LDSM4(b[j], baddr);
            }
#pragma unroll
            for (int mi = 0; mi < 4; mi++)
#pragma unroll
                for (int ni = 0; ni < 8; ni++)
                    MMA16816(acc[mi][ni], ah[mi], b[ni>>1][(ni&1)*2], b[ni>>1][(ni&1)*2+1]);
#pragma unroll
            for (int mi = 0; mi < 4; mi++)
#pragma unroll
                for (int ni = 0; ni < 8; ni++)
                    MMA16816(acc[mi][ni], al[mi], b[ni>>1][(ni&1)*2], b[ni>>1][(ni&1)*2+1]);
#pragma unroll
            for (int j = 0; j < 4; j++) {
                uint32_t baddr = st + 2*TILE_A + TILE_B +
                    swz((uint32_t)(b_row + j*16), (uint32_t)(b_ch + ks*2));
                LDSM4(b[j], baddr);
            }
#pragma unroll
            for (int mi = 0; mi < 4; mi++)
#pragma unroll
                for (int ni = 0; ni < 8; ni++)
                    MMA16816(acc[mi][ni], ah[mi], b[ni>>1][(ni&1)*2], b[ni>>1][(ni&1)*2+1]);
        }

        __syncthreads();
        if (it + GSTAGES < 64) load_stage(it + GSTAGES, stage);
        CP_COMMIT();
    }

    const int erow = bm + wm*64 + (lane >> 2);
    const int ecol = bn + wn*64 + (lane & 3) * 2;
#pragma unroll
    for (int mi = 0; mi < 4; mi++)
#pragma unroll
        for (int ni = 0; ni < 8; ni++) {
            size_t r0 = (size_t)(erow + mi*16) * CC + ecol + ni*8;
            *(float2*)&Y[r0]        = make_float2(acc[mi][ni][0], acc[mi][ni][1]);
            *(float2*)&Y[r0 + 8*CC] = make_float2(acc[mi][ni][2], acc[mi][ni][3]);
        }
}

// ---------------------------------------------------------------------------
// K3: batched LoRA stage 1 (5 column-tile jobs in one launch)
//     U[:, col0:col0+64] = act( X[BT,2048] @ G[2048,D][:, col0:col0+64] )
// ---------------------------------------------------------------------------
struct Lora1Job  { const float* X; const float* G; float* U; int D; int col0; int act; };
struct Lora1Jobs { Lora1Job j[5]; };

__global__ __launch_bounds__(256) void lora1_all_kernel(Lora1Jobs jobs)
{
    const Lora1Job jb = jobs.j[blockIdx.y];
    const float* __restrict__ X = jb.X;
    const float* __restrict__ G = jb.G;
    const int D = jb.D, col0 = jb.col0, act = jb.act;

    constexpr int BM = 16, BK = 32;
    __shared__ float Xs[BK][BM+1];
    __shared__ float Gs[BK][64];

    const int tid = threadIdx.x;
    const int bm = blockIdx.x * BM;
    const int c  = tid & 63;          // local column
    const int rg = tid >> 6;          // 0..3

    float acc[4] = {0.f, 0.f, 0.f, 0.f};

    for (int k0 = 0; k0 < 2048; k0 += BK) {
        if (tid < 128) {
            int row = tid >> 3, cc = (tid & 7) << 2;
            float4 xv = *(const float4*)&X[(size_t)(bm+row)*CC + k0 + cc];
            Xs[cc+0][row]=xv.x; Xs[cc+1][row]=xv.y;
            Xs[cc+2][row]=xv.z; Xs[cc+3][row]=xv.w;
        }
#pragma unroll
        for (int i = 0; i < 2; i++) {
            int lin = tid + (i << 8);          // 0..511
            int kr = lin >> 4;                 // 0..31
            int cc = (lin & 15) << 2;          // 0..60
            float4 gv;
            if (col0 + cc < D)
                gv = *(const float4*)&G[(size_t)(k0+kr)*D + col0 + cc];
            else
                gv = make_float4(0.f, 0.f, 0.f, 0.f);
            *(float4*)&Gs[kr][cc] = gv;
        }
        __syncthreads();
#pragma unroll
        for (int kk = 0; kk < BK; kk++) {
            float gv = Gs[kk][c];
#pragma unroll
            for (int i = 0; i < 4; i++)
                acc[i] += Xs[kk][rg + i*4] * gv;
        }
        __syncthreads();
    }
    if (col0 + c < D) {
#pragma unroll
        for (int i = 0; i < 4; i++) {
            float y = acc[i];
            if (act == 1) y = tanhf(y);
            else if (act == 2) y = 1.f/(1.f+expf(-y));
            jb.U[(size_t)(bm + rg + i*4)*D + col0 + c] = y;
        }
    }
}

// ---------------------------------------------------------------------------
// K4: batched LoRA stage 2 + epilogue (4 jobs in one launch)
//   mode 0: decay = e^{-1/2} * sigmoid(acc + bias)
//   mode 1: sigmoid(acc + bias)
//   mode 2: v lerp: out = e1 + (e2 - e1)*sigmoid(acc + bias)
//   mode 3: plain
// ---------------------------------------------------------------------------
struct Stage2Job  { const float* U; const float* V2; const float* bias;
                    float* out; const float* e1; const float* e2; int D; int mode; };
struct Stage2Jobs { Stage2Job j[4]; };

__global__ __launch_bounds__(256) void stage2_all_kernel(Stage2Jobs jobs)
{
    const Stage2Job jb = jobs.j[blockIdx.z];
    const int D = jb.D, mode = jb.mode;

    constexpr int ROWS = 32;
    __shared__ float Us[ROWS][128];
    const int tid = threadIdx.x;
    const int row0 = blockIdx.y * ROWS;
    const int c = blockIdx.x * 256 + tid;

    {
        const int q = D >> 2;                 // float4s per row
        const int total = ROWS * q;
        for (int idx = tid; idx < total; idx += 256) {
            int rr = idx / q;
            int cc = (idx - rr*q) << 2;
            *(float4*)&Us[rr][cc] = *(const float4*)&jb.U[(size_t)(row0+rr)*D + cc];
        }
    }
    __syncthreads();

    float acc[ROWS];
#pragma unroll
    for (int r = 0; r < ROWS; r++) acc[r] = 0.f;

#pragma unroll 4
    for (int d0 = 0; d0 < D; d0 += 4) {
        float v0 = jb.V2[(size_t)(d0+0)*CC + c];
        float v1 = jb.V2[(size_t)(d0+1)*CC + c];
        float v2 = jb.V2[(size_t)(d0+2)*CC + c];
        float v3 = jb.V2[(size_t)(d0+3)*CC + c];
#pragma unroll
        for (int r = 0; r < ROWS; r++) {
            float4 u = *(const float4*)&Us[r][d0];
            acc[r] += u.x*v0 + u.y*v1 + u.z*v2 + u.w*v3;
        }
    }
    float bv = (mode == 3) ? 0.f : jb.bias[c];
#pragma unroll
    for (int r = 0; r < ROWS; r++) {
        size_t idx = (size_t)(row0+r)*CC + c;
        float y = acc[r] + bv;
        if (mode == 0)      jb.out[idx] = 0.6065306597126334f * (1.f/(1.f+expf(-y)));
        else if (mode == 1) jb.out[idx] = 1.f/(1.f+expf(-y));
        else if (mode == 2) {
            float s = 1.f/(1.f+expf(-y));
            float vr = jb.e1[idx];
            jb.out[idx] = vr + (jb.e2[idx]-vr)*s;
        } else              jb.out[idx] = y;
    }
}

// ---------------------------------------------------------------------------
// K5: per-(b,t,h) prep
// ---------------------------------------------------------------------------
__global__ __launch_bounds__(256) void prep_kernel(
    const float* __restrict__ k, const float* __restrict__ asig,
    const float* __restrict__ kkvec, const float* __restrict__ kavec,
    float* __restrict__ aw, float* __restrict__ bw, float* __restrict__ kf)
{
    const int tid = threadIdx.x;
    const int g = tid >> 6, n = tid & 63;
    const size_t head = (size_t)blockIdx.x*4 + g;
    const size_t idx = head*64 + n;
    const int c = (int)(idx & (CC-1));

    float kv = k[idx];
    float kk = kv * kkvec[c];
    float ss = kk*kk;
#pragma unroll
    for (int off=16; off; off>>=1) ss += __shfl_xor_sync(0xffffffffu, ss, off);
    __shared__ float red[8];
    if ((tid & 31)==0) red[tid>>5] = ss;
    __syncthreads();
    float tot = red[g*2] + red[g*2+1];
    float inv = 1.f / fmaxf(sqrtf(tot), 1e-12f);
    float kkn = kk * inv;
    float a = asig[idx];
    aw[idx] = -kkn;
    bw[idx] = kkn * a;
    kf[idx] = kv + kavec[c]*(kv*a - kv);
}

// ---------------------------------------------------------------------------
// K6: WKV7 recurrence, v-split x2.
//     Block = (b,h,vhalf): 32 v-rows x 64 k. 128 threads: thread=(v-row, k-quarter),
//     S[16]/thread, quad shuffle reductions, 2-deep global->smem prefetch.
// ---------------------------------------------------------------------------
__global__ __launch_bounds__(128) void wkv_kernel(
    const float* __restrict__ r, const float* __restrict__ k,
    const float* __restrict__ v, const float* __restrict__ d,
    const float* __restrict__ aw, const float* __restrict__ bw,
    const float* __restrict__ s0, float* __restrict__ o)
{
    const int blk = blockIdx.x;           // 0..127
    const int bh = blk >> 1;              // 0..63
    const int vh = blk & 1;               // v-half
    const int b = bh >> 5, hh = bh & 31;
    const int tid = threadIdx.x;
    const int vr = tid >> 2;              // 0..31 (local v-row)
    const int vg = vh*32 + vr;            // global v-row
    const int kq = tid & 3;
    const int koff = kq * 16;
    const int n = tid & 63;

    float S[16];
    {
        const float* sp = s0 + ((size_t)bh*64 + vg)*64 + koff;
#pragma unroll
        for (int i=0;i<16;i++) S[i] = sp[i];
    }

    __shared__ float sh[2][6][64];        // 0=r 1=k 2=v 3=d 4=aw 5=bw
    const size_t rowbase = (size_t)b*TT*CC + hh*64;

    float p0, p1, p2;
    {
        size_t idx = rowbase + n;
        if (tid < 64) { sh[0][0][n]=r[idx]; sh[0][1][n]=k[idx]; sh[0][2][n]=v[idx]; }
        else          { sh[0][3][n]=d[idx]; sh[0][4][n]=aw[idx]; sh[0][5][n]=bw[idx]; }
    }
    {
        size_t idx = rowbase + (size_t)1*CC + n;
        if (tid < 64) { p0=r[idx]; p1=k[idx]; p2=v[idx]; }
        else          { p0=d[idx]; p1=aw[idx]; p2=bw[idx]; }
    }
    __syncthreads();

    for (int t = 0; t < TT; t++) {
        const int buf = t & 1;
        if (t+1 < TT) {
            if (tid < 64) { sh[buf^1][0][n]=p0; sh[buf^1][1][n]=p1; sh[buf^1][2][n]=p2; }
            else          { sh[buf^1][3][n]=p0; sh[buf^1][4][n]=p1; sh[buf^1][5][n]=p2; }
        }
        if (t+2 < TT) {
            size_t idx = rowbase + (size_t)(t+2)*CC + n;
            if (tid < 64) { p0=r[idx]; p1=k[idx]; p2=v[idx]; }
            else          { p0=d[idx]; p1=aw[idx]; p2=bw[idx]; }
        }

        const float* shr = sh[buf][0];
        const float* shk = sh[buf][1];
        const float* shv = sh[buf][2];
        const float* shd = sh[buf][3];
        const float* sha = sh[buf][4];
        const float* shb = sh[buf][5];

        float sa0=0.f, sa1=0.f, sa2=0.f, sa3=0.f;
#pragma unroll
        for (int i=0;i<16;i+=4){
            float4 a4 = *(const float4*)&sha[koff+i];
            sa0 += S[i+0]*a4.x; sa1 += S[i+1]*a4.y;
            sa2 += S[i+2]*a4.z; sa3 += S[i+3]*a4.w;
        }
        float sa = (sa0+sa1)+(sa2+sa3);
        sa += __shfl_xor_sync(0xffffffffu, sa, 1);
        sa += __shfl_xor_sync(0xffffffffu, sa, 2);

        const float vt = shv[vg];
        float o0=0.f,o1=0.f,o2=0.f,o3=0.f;
#pragma unroll
        for (int i=0;i<16;i+=4){
            float4 d4 = *(const float4*)&shd[koff+i];
            float4 b4 = *(const float4*)&shb[koff+i];
            float4 k4 = *(const float4*)&shk[koff+i];
            float4 r4 = *(const float4*)&shr[koff+i];
            S[i+0] = S[i+0]*d4.x + sa*b4.x + vt*k4.x;
            S[i+1] = S[i+1]*d4.y + sa*b4.y + vt*k4.y;
            S[i+2] = S[i+2]*d4.z + sa*b4.z + vt*k4.z;
            S[i+3] = S[i+3]*d4.w + sa*b4.w + vt*k4.w;
            o0 += S[i+0]*r4.x; o1 += S[i+1]*r4.y;
            o2 += S[i+2]*r4.z; o3 += S[i+3]*r4.w;
        }
        float oo = (o0+o1)+(o2+o3);
        oo += __shfl_xor_sync(0xffffffffu, oo, 1);
        oo += __shfl_xor_sync(0xffffffffu, oo, 2);
        if (kq == 0) o[rowbase + (size_t)t*CC + vg] = oo;
        __syncthreads();
    }
}

// ---------------------------------------------------------------------------
// K7: group norm + per-head bonus + gate multiply -> bf16 hi/lo
// ---------------------------------------------------------------------------
__global__ __launch_bounds__(256) void gn_kernel(
    const float* __restrict__ o, const float* __restrict__ r,
    const float* __restrict__ kf, const float* __restrict__ vf,
    const float* __restrict__ gg, const float* __restrict__ rk,
    const float* __restrict__ gnw, const float* __restrict__ gnb,
    __nv_bfloat16* __restrict__ xoh, __nv_bfloat16* __restrict__ xol)
{
    const int tid = threadIdx.x;
    const int g = tid >> 6, n = tid & 63;
    const size_t head = (size_t)blockIdx.x*4 + g;
    const int h = (int)(head & (HH-1));
    const size_t idx = head*64 + n;
    const int c = h*64 + n;

    float ov = o[idx];
    float rv = r[idx], kv = kf[idx];
    float s1 = ov, s2 = ov*ov, s3 = rv*kv*rk[c];
#pragma unroll
    for (int off=16; off; off>>=1){
        s1 += __shfl_xor_sync(0xffffffffu, s1, off);
        s2 += __shfl_xor_sync(0xffffffffu, s2, off);
        s3 += __shfl_xor_sync(0xffffffffu, s3, off);
    }
    __shared__ float red[8][3];
    if ((tid & 31)==0){ int w = tid>>5; red[w][0]=s1; red[w][1]=s2; red[w][2]=s3; }
    __syncthreads();
    float S1 = red[g*2][0]+red[g*2+1][0];
    float S2 = red[g*2][1]+red[g*2+1][1];
    float S3 = red[g*2][2]+red[g*2+1][2];
    float mu = S1*(1.f/64.f);
    float var = S2*(1.f/64.f) - mu*mu;
    float y = (ov-mu)*rsqrtf(var + 6.4e-4f)*gnw[c] + gnb[c] + S3*vf[idx];
    float xo = y * gg[idx];
    __nv_bfloat16 hv, lv;
    split_hilo(xo, hv, lv);
    xoh[idx] = hv;
    xol[idx] = lv;
}

// ---------------------------------------------------------------------------
// Launch
// ---------------------------------------------------------------------------
extern "C" void kernel_launch(void* const* d_in, const int* in_sizes, int n_in,
                              void* d_out, int out_size)
{
    const float* h      = (const float*)d_in[0];
    const float* shift  = (const float*)d_in[1];
    const float* s0     = (const float*)d_in[2];
    const float* vfirst = (const float*)d_in[3];
    const float* x_r = (const float*)d_in[4];
    const float* x_w = (const float*)d_in[5];
    const float* x_k = (const float*)d_in[6];
    const float* x_v = (const float*)d_in[7];
    const float* x_a = (const float*)d_in[8];
    const float* x_g = (const float*)d_in[9];
    const float* w0 = (const float*)d_in[10];
    const float* w1 = (const float*)d_in[11];
    const float* w2 = (const float*)d_in[12];
    const float* a0 = (const float*)d_in[13];
    const float* a1 = (const float*)d_in[14];
    const float* a2 = (const float*)d_in[15];
    const float* v0 = (const float*)d_in[16];
    const float* v1 = (const float*)d_in[17];
    const float* v2 = (const float*)d_in[18];
    const float* g1 = (const float*)d_in[19];
    const float* g2 = (const float*)d_in[20];
    const float* k_k = (const float*)d_in[21];
    const float* k_a = (const float*)d_in[22];
    const float* r_k = (const float*)d_in[23];
    const float* W_r = (const float*)d_in[24];
    const float* W_k = (const float*)d_in[25];
    const float* W_v = (const float*)d_in[26];
    const float* W_o = (const float*)d_in[27];
    const float* gnw = (const float*)d_in[28];
    const float* gnb = (const float*)d_in[29];
    float* out = (float*)d_out;

    float* S = nullptr;
    cudaGetSymbolAddress((void**)&S, g_scratch);

    float* xw    = S + (size_t)S_XW*BTC;
    float* xa    = S + (size_t)S_XA*BTC;
    float* xv    = S + (size_t)S_XV*BTC;
    float* xg    = S + (size_t)S_XG*BTC;
    float* rb    = S + (size_t)S_R*BTC;
    float* kb    = S + (size_t)S_K*BTC;
    float* vb    = S + (size_t)S_V*BTC;
    float* decay = S + (size_t)S_DECAY*BTC;
    float* asig  = S + (size_t)S_ASIG*BTC;
    float* gbuf  = S + (size_t)S_G*BTC;
    float* awb   = S + (size_t)S_AW*BTC;
    float* bwb   = S + (size_t)S_BW*BTC;
    float* kfb   = S + (size_t)S_KF*BTC;
    float* vfb   = S + (size_t)S_VF*BTC;
    float* ob    = S + (size_t)S_O*BTC;

    __nv_bfloat16* bfb = (__nv_bfloat16*)(S + BF16_BASE);
#define BF(i) (bfb + (size_t)(i)*BTC)
    __nv_bfloat16 *xrh=BF(B_XRH), *xrl=BF(B_XRL), *xkh=BF(B_XKH), *xkl=BF(B_XKL);
    __nv_bfloat16 *xvh=BF(B_XVH), *xvl=BF(B_XVL), *xoh=BF(B_XOH), *xol=BF(B_XOL);
    __nv_bfloat16 *wrh=BF(B_WRH), *wrl=BF(B_WRL), *wkh=BF(B_WKH), *wkl=BF(B_WKL);
    __nv_bfloat16 *wvh=BF(B_WVH), *wvl=BF(B_WVL), *woh=BF(B_WOH), *wol=BF(B_WOL);
#undef BF
    float* Uw = S + U_W_OFF;  float* Ua = S + U_A_OFF;
    float* Uv = S + U_V_OFF;  float* Ug = S + U_G_OFF;

    cudaFuncSetAttribute(gemm_bf16x3,
                         cudaFuncAttributeMaxDynamicSharedMemorySize, GEMM_SMEM);

    // 0. weight conversions (one batched launch)
    CvtJobs cj;
    cj.x[0]=W_r; cj.hi[0]=wrh; cj.lo[0]=wrl;
    cj.x[1]=W_k; cj.hi[1]=wkh; cj.lo[1]=wkl;
    cj.x[2]=W_v; cj.hi[2]=wvh; cj.lo[2]=wvl;
    cj.x[3]=W_o; cj.hi[3]=woh; cj.lo[3]=wol;
    cvt_all_kernel<<<dim3(4096, 4), 256>>>(cj);

    // 1. token shift + mixes
    mix_kernel<<<4096, 256>>>(h, shift, x_r, x_w, x_k, x_v, x_a, x_g,
                              xrh, xrl, xw, xkh, xkl, xv, xvh, xvl, xa, xg);

    // 2. big r/k/v projections (one batched HMMA launch, 3 jobs)
    GemmJobs gj;
    gj.j[0] = { xrh, xrl, wrh, wrl, rb };
    gj.j[1] = { xkh, xkl, wkh, wkl, kb };
    gj.j[2] = { xvh, xvl, wvh, wvl, vb };
    gemm_bf16x3<<<dim3(8, 16, 3), 256, GEMM_SMEM>>>(gj);

    // 3. LoRA stage 1 (one batched launch, 5 column-tile jobs)
    Lora1Jobs lj;
    lj.j[0] = { xw, w1, Uw,  64, 0, 1 };   // tanh
    lj.j[1] = { xa, a1, Ua,  64, 0, 0 };
    lj.j[2] = { xv, v1, Uv,  32, 0, 0 };
    lj.j[3] = { xg, g1, Ug, 128, 0, 2 };   // sigmoid
    lj.j[4] = { xg, g1, Ug, 128, 64, 2 };  // sigmoid (cols 64..127)
    lora1_all_kernel<<<dim3(128, 5), 256>>>(lj);

    // 4. LoRA stage 2 + epilogues (one batched launch, 4 jobs)
    Stage2Jobs sj;
    sj.j[0] = { Uw, w2, w0, decay, nullptr, nullptr,  64, 0 };
    sj.j[1] = { Ua, a2, a0, asig,  nullptr, nullptr,  64, 1 };
    sj.j[2] = { Uv, v2, v0, vfb,   vb,      vfirst,   32, 2 };
    sj.j[3] = { Ug, g2, nullptr, gbuf, nullptr, nullptr, 128, 3 };
    stage2_all_kernel<<<dim3(8, 64, 4), 256>>>(sj);

    // 5. kk-normalize / k lerp prep
    prep_kernel<<<BT*HH/4, 256>>>(kb, asig, k_k, k_a, awb, bwb, kfb);

    // 6. WKV7 recurrence (v-split x2: 128 blocks)
    wkv_kernel<<<BB*HH*2, 128>>>(rb, kfb, vfb, decay, awb, bwb, s0, ob);

    // 7. group norm + bonus + gate
    gn_kernel<<<BT*HH/4, 256>>>(ob, rb, kfb, vfb, gbuf, r_k, gnw, gnb, xoh, xol);

    // 8. output projection (single job)
    GemmJobs oj;
    oj.j[0] = { xoh, xol, woh, wol, out };
    oj.j[1] = oj.j[0];
    oj.j[2] = oj.j[0];
    gemm_bf16x3<<<dim3(8, 16, 1), 256, GEMM_SMEM>>>(oj);
}

// round 6
// speedup vs baseline: 1.7661x; 1.0908x over previous
#include <cuda_runtime.h>
#include <cuda_bf16.h>
#include <math.h>
#include <cstdint>

// Problem constants
#define BB 2
#define TT 1024
#define CC 2048
#define HH 32
#define NN 64
#define BT (BB*TT)              // 2048
#define BTC (BB*TT*CC)          // 4194304  (== CC*CC)

// ---------------------------------------------------------------------------
// Scratch (static device memory)
// ---------------------------------------------------------------------------
enum { S_XW=0, S_XA, S_XV, S_XG, S_R, S_K, S_V,
       S_DECAY, S_ASIG, S_G, S_AW, S_BW, S_KF, S_VF, S_O, N_F32 };
enum { B_XRH=0, B_XRL, B_XKH, B_XKL, B_XVH, B_XVL, B_XOH, B_XOL,
       B_WRH, B_WRL, B_WKH, B_WKL, B_WVH, B_WVL, B_WOH, B_WOL, N_BF16 };
#define BF16_BASE ((size_t)N_F32*BTC)                 // in floats
#define U_W_OFF   (BF16_BASE + (size_t)N_BF16*BTC/2)
#define U_A_OFF   (U_W_OFF + (size_t)BT*64)
#define U_V_OFF   (U_A_OFF + (size_t)BT*64)
#define U_G_OFF   (U_V_OFF + (size_t)BT*32)
#define BR_OFF    (U_G_OFF + (size_t)BT*128)
#define KR_OFF    (BR_OFF + (size_t)BB*HH*TT)
#define SCRATCH_FLOATS (KR_OFF + (size_t)BB*HH*TT)

__device__ float g_scratch[SCRATCH_FLOATS];

// ---------------------------------------------------------------------------
// PTX helpers (plain sm_103-compatible)
// ---------------------------------------------------------------------------
__device__ __forceinline__ uint32_t smem_u32(const void* p) {
    uint32_t a;
    asm("{ .reg .u64 t; cvta.to.shared.u64 t, %1; cvt.u32.u64 %0, t; }" : "=r"(a) : "l"(p));
    return a;
}
#define CP16(dst, src) \
    asm volatile("cp.async.cg.shared.global [%0], [%1], 16;" :: "r"(dst), "l"(src))
#define CP_COMMIT() asm volatile("cp.async.commit_group;" ::: "memory")
#define CP_WAIT2()  asm volatile("cp.async.wait_group 2;"  ::: "memory")
#define LDSM4(r, addr) \
    asm volatile("ldmatrix.sync.aligned.m8n8.x4.shared.b16 {%0,%1,%2,%3}, [%4];" \
        : "=r"((r)[0]), "=r"((r)[1]), "=r"((r)[2]), "=r"((r)[3]) : "r"(addr))
#define MMA16816(d, a, b0, b1) \
    asm volatile("mma.sync.aligned.m16n8k16.row.col.f32.bf16.bf16.f32 " \
        "{%0,%1,%2,%3}, {%4,%5,%6,%7}, {%8,%9}, {%0,%1,%2,%3};" \
        : "+f"((d)[0]), "+f"((d)[1]), "+f"((d)[2]), "+f"((d)[3]) \
        : "r"((a)[0]), "r"((a)[1]), "r"((a)[2]), "r"((a)[3]), "r"(b0), "r"(b1))

// ---------------------------------------------------------------------------
// hi/lo split helpers
// ---------------------------------------------------------------------------
__device__ __forceinline__ void split_hilo(float v, __nv_bfloat16& h, __nv_bfloat16& l) {
    h = __float2bfloat16(v);
    l = __float2bfloat16(v - __bfloat162float(h));
}
__device__ __forceinline__ void store_hilo4(__nv_bfloat16* hi, __nv_bfloat16* lo,
                                            size_t off, float4 v) {
    __nv_bfloat16 hv[4], lv[4];
    split_hilo(v.x, hv[0], lv[0]); split_hilo(v.y, hv[1], lv[1]);
    split_hilo(v.z, hv[2], lv[2]); split_hilo(v.w, hv[3], lv[3]);
    *(uint2*)&hi[off] = *(uint2*)hv;
    *(uint2*)&lo[off] = *(uint2*)lv;
}

// ---------------------------------------------------------------------------
// K0: batched fp32 -> bf16 hi/lo conversion (4 weights in one launch)
// ---------------------------------------------------------------------------
struct CvtJobs { const float* x[4]; __nv_bfloat16* hi[4]; __nv_bfloat16* lo[4]; };

__global__ __launch_bounds__(256) void cvt_all_kernel(CvtJobs jobs)
{
    const int z = blockIdx.y;
    size_t i = ((size_t)blockIdx.x * 256 + threadIdx.x) * 4;
    float4 v = *(const float4*)&jobs.x[z][i];
    store_hilo4(jobs.hi[z], jobs.lo[z], i, v);
}

// ---------------------------------------------------------------------------
// K1: token shift + 6-way mix
// ---------------------------------------------------------------------------
__global__ __launch_bounds__(256) void mix_kernel(
    const float* __restrict__ h, const float* __restrict__ shift,
    const float* __restrict__ mr, const float* __restrict__ mw,
    const float* __restrict__ mk, const float* __restrict__ mv,
    const float* __restrict__ ma, const float* __restrict__ mg,
    __nv_bfloat16* __restrict__ xrh, __nv_bfloat16* __restrict__ xrl,
    float* __restrict__ oxw,
    __nv_bfloat16* __restrict__ xkh, __nv_bfloat16* __restrict__ xkl,
    float* __restrict__ oxv,
    __nv_bfloat16* __restrict__ xvh, __nv_bfloat16* __restrict__ xvl,
    float* __restrict__ oxa, float* __restrict__ oxg)
{
    int gid = blockIdx.x * 256 + threadIdx.x;
    int row = gid >> 9;
    int c   = (gid & 511) << 2;
    int t   = row & (TT-1);
    int b   = row >> 10;
    size_t off = (size_t)row * CC + c;

    float4 hv = *(const float4*)&h[off];
    float4 pv;
    if (t == 0) pv = *(const float4*)&shift[(size_t)b*CC + c];
    else        pv = *(const float4*)&h[off - CC];
    float4 xx = make_float4(pv.x-hv.x, pv.y-hv.y, pv.z-hv.z, pv.w-hv.w);

#define MIXV(mvec, o)                                                 \
    {   float4 m = *(const float4*)&mvec[c];                          \
        o = make_float4(hv.x + xx.x*m.x, hv.y + xx.y*m.y,             \
                        hv.z + xx.z*m.z, hv.w + xx.w*m.w); }
    float4 vr; MIXV(mr, vr); store_hilo4(xrh, xrl, off, vr);
    float4 vw; MIXV(mw, vw); *(float4*)&oxw[off] = vw;
    float4 vk; MIXV(mk, vk); store_hilo4(xkh, xkl, off, vk);
    float4 vv; MIXV(mv, vv); *(float4*)&oxv[off] = vv; store_hilo4(xvh, xvl, off, vv);
    float4 va; MIXV(ma, va); *(float4*)&oxa[off] = va;
    float4 vg; MIXV(mg, vg); *(float4*)&oxg[off] = vg;
#undef MIXV
}

// ---------------------------------------------------------------------------
// K2: HMMA bf16x3 GEMM (batched over blockIdx.z jobs)
// ---------------------------------------------------------------------------
#define GSTAGES 3
#define TILE_A 8192              // 128 rows x 64 B
#define TILE_B 16384             // 256 rows x 64 B
#define STAGE_B (2*TILE_A + 2*TILE_B)   // 49152
#define GEMM_SMEM (GSTAGES*STAGE_B)     // 147456

struct GemmJob  { const __nv_bfloat16 *Ah, *Al, *Bh, *Bl; float* Y; };
struct GemmJobs { GemmJob j[3]; };

__device__ __forceinline__ uint32_t swz(uint32_t row, uint32_t chunk) {
    return row*64u + ((chunk ^ ((row >> 1) & 3u)) << 4);
}

__global__ __launch_bounds__(256, 1) void gemm_bf16x3(GemmJobs jobs)
{
    extern __shared__ char dynsmem[];
    const GemmJob gj = jobs.j[blockIdx.z];
    const __nv_bfloat16* __restrict__ Ahi = gj.Ah;
    const __nv_bfloat16* __restrict__ Alo = gj.Al;
    const __nv_bfloat16* __restrict__ Bhi = gj.Bh;
    const __nv_bfloat16* __restrict__ Blo = gj.Bl;
    float* __restrict__ Y = gj.Y;

    const uint32_t sb = smem_u32(dynsmem);
    const int tid  = threadIdx.x;
    const int lane = tid & 31;
    const int warp = tid >> 5;
    const int wm = warp >> 2;
    const int wn = warp & 3;
    const int bm = blockIdx.y << 7;
    const int bn = blockIdx.x << 8;

    auto load_stage = [&](int chunk, int stage) {
        const uint32_t st = sb + (uint32_t)stage * STAGE_B;
        const int k0 = chunk << 5;
#pragma unroll
        for (int i = 0; i < 2; i++) {
            int idx = tid + (i << 8);
            int row = idx >> 2, ch = idx & 3;
            uint32_t d = st + swz(row, ch);
            size_t g = (size_t)(bm + row) * CC + k0 + ch * 8;
            CP16(d,          Ahi + g);
            CP16(d + TILE_A, Alo + g);
        }
#pragma unroll
        for (int i = 0; i < 4; i++) {
            int idx = tid + (i << 8);
            int row = idx >> 2, ch = idx & 3;
            uint32_t d = st + 2*TILE_A + swz(row, ch);
            size_t g = (size_t)(bn + row) * CC + k0 + ch * 8;
            CP16(d,          Bhi + g);
            CP16(d + TILE_B, Blo + g);
        }
    };

    float acc[4][8][4];
#pragma unroll
    for (int mi=0;mi<4;mi++)
#pragma unroll
        for (int ni=0;ni<8;ni++)
#pragma unroll
            for (int j=0;j<4;j++) acc[mi][ni][j] = 0.f;

#pragma unroll
    for (int s = 0; s < GSTAGES; s++) { load_stage(s, s); CP_COMMIT(); }

    const int a_row = wm*64 + (lane & 7) + ((lane >> 3) & 1) * 8;
    const int a_ch  = (lane >> 4);
    const int b_row = wn*64 + (lane & 7) + (lane >> 4) * 8;
    const int b_ch  = ((lane >> 3) & 1);

    for (int it = 0; it < 64; it++) {
        const int stage = it % GSTAGES;
        const uint32_t st = sb + (uint32_t)stage * STAGE_B;
        CP_WAIT2();
        __syncthreads();

#pragma unroll
        for (int ks = 0; ks < 2; ks++) {
            uint32_t ah[4][4], al[4][4], b[4][4];
#pragma unroll
            for (int mi = 0; mi < 4; mi++) {
                uint32_t a = st + swz((uint32_t)(a_row + mi*16), (uint32_t)(a_ch + ks*2));
                LDSM4(ah[mi], a);
                LDSM4(al[mi], a + TILE_A);
            }
#pragma unroll
            for (int j = 0; j < 4; j++) {
                uint32_t baddr = st + 2*TILE_A +
                    swz((uint32_t)(b_row + j*16), (uint32_t)(b_ch + ks*2));
                LDSM4(b[j], baddr);
            }
#pragma unroll
            for (int mi = 0; mi < 4; mi++)
#pragma unroll
                for (int ni = 0; ni < 8; ni++)
                    MMA16816(acc[mi][ni], ah[mi], b[ni>>1][(ni&1)*2], b[ni>>1][(ni&1)*2+1]);
#pragma unroll
            for (int mi = 0; mi < 4; mi++)
#pragma unroll
                for (int ni = 0; ni < 8; ni++)
                    MMA16816(acc[mi][ni], al[mi], b[ni>>1][(ni&1)*2], b[ni>>1][(ni&1)*2+1]);
#pragma unroll
            for (int j = 0; j < 4; j++) {
                uint32_t baddr = st + 2*TILE_A + TILE_B +
                    swz((uint32_t)(b_row + j*16), (uint32_t)(b_ch + ks*2));
                LDSM4(b[j], baddr);
            }
#pragma unroll
            for (int mi = 0; mi < 4; mi++)
#pragma unroll
                for (int ni = 0; ni < 8; ni++)
                    MMA16816(acc[mi][ni], ah[mi], b[ni>>1][(ni&1)*2], b[ni>>1][(ni&1)*2+1]);
        }

        __syncthreads();
        if (it + GSTAGES < 64) load_stage(it + GSTAGES, stage);
        CP_COMMIT();
    }

    const int erow = bm + wm*64 + (lane >> 2);
    const int ecol = bn + wn*64 + (lane & 3) * 2;
#pragma unroll
    for (int mi = 0; mi < 4; mi++)
#pragma unroll
        for (int ni = 0; ni < 8; ni++) {
            size_t r0 = (size_t)(erow + mi*16) * CC + ecol + ni*8;
            *(float2*)&Y[r0]        = make_float2(acc[mi][ni][0], acc[mi][ni][1]);
            *(float2*)&Y[r0 + 8*CC] = make_float2(acc[mi][ni][2], acc[mi][ni][3]);
        }
}

// ---------------------------------------------------------------------------
// K3: batched LoRA stage 1 — register-tiled 64x64 block, 4x4 thread tile.
//     U[:, col0:col0+64] = act( X[BT,2048] @ G[2048,D][:, col0:col0+64] )
// ---------------------------------------------------------------------------
struct Lora1Job  { const float* X; const float* G; float* U; int D; int col0; int act; };
struct Lora1Jobs { Lora1Job j[5]; };

__global__ __launch_bounds__(256) void lora1_all_kernel(Lora1Jobs jobs)
{
    const Lora1Job jb = jobs.j[blockIdx.y];
    const float* __restrict__ X = jb.X;
    const float* __restrict__ G = jb.G;
    const int D = jb.D, col0 = jb.col0, act = jb.act;

    __shared__ float Xs[32][68];   // [k][row], transposed on store
    __shared__ float Gs[32][64];   // [k][col]

    const int tid = threadIdx.x;
    const int bm = blockIdx.x * 64;
    const int tx = tid & 15;       // col group
    const int ty = tid >> 4;       // row group

    // X mapping: lin -> row = lin & 63, kc4 = lin >> 6 (8 float4 cols)
    // G mapping: lin -> kr = lin >> 4, cc = (lin & 15)*4
    float4 px[2], pg[2];
    const int xrow = tid & 63;
    const int xkc0 = (tid >> 6) << 2;          // 0,4,8,12 ; +16 for i=1
    const int gkr0 = tid >> 4;                 // 0..15 ; +16 for i=1
    const int gcc  = (tid & 15) << 2;

    auto gload = [&](int k0) {
#pragma unroll
        for (int i = 0; i < 2; i++) {
            px[i] = *(const float4*)&X[(size_t)(bm + xrow)*CC + k0 + xkc0 + i*16];
            if (col0 + gcc < D)
                pg[i] = *(const float4*)&G[(size_t)(k0 + gkr0 + i*16)*D + col0 + gcc];
            else
                pg[i] = make_float4(0.f, 0.f, 0.f, 0.f);
        }
    };
    auto sstore = [&]() {
#pragma unroll
        for (int i = 0; i < 2; i++) {
            int kc = xkc0 + i*16;
            Xs[kc+0][xrow] = px[i].x; Xs[kc+1][xrow] = px[i].y;
            Xs[kc+2][xrow] = px[i].z; Xs[kc+3][xrow] = px[i].w;
            *(float4*)&Gs[gkr0 + i*16][gcc] = pg[i];
        }
    };

    float acc[4][4];
#pragma unroll
    for (int i=0;i<4;i++)
#pragma unroll
        for (int j=0;j<4;j++) acc[i][j] = 0.f;

    gload(0); sstore(); __syncthreads();

    for (int k0 = 32; k0 <= 2048; k0 += 32) {
        if (k0 < 2048) gload(k0);
#pragma unroll
        for (int kk = 0; kk < 32; kk++) {
            float4 xa = *(const float4*)&Xs[kk][ty*4];
            float4 gb = *(const float4*)&Gs[kk][tx*4];
            float xv[4] = {xa.x, xa.y, xa.z, xa.w};
            float gv[4] = {gb.x, gb.y, gb.z, gb.w};
#pragma unroll
            for (int i=0;i<4;i++)
#pragma unroll
                for (int j=0;j<4;j++)
                    acc[i][j] += xv[i]*gv[j];
        }
        __syncthreads();
        if (k0 < 2048) { sstore(); __syncthreads(); }
    }

#pragma unroll
    for (int i=0;i<4;i++) {
        int row = bm + ty*4 + i;
#pragma unroll
        for (int j=0;j<4;j++) {
            int col = col0 + tx*4 + j;
            if (col < D) {
                float y = acc[i][j];
                if (act == 1) y = tanhf(y);
                else if (act == 2) y = 1.f/(1.f+expf(-y));
                jb.U[(size_t)row*D + col] = y;
            }
        }
    }
}

// ---------------------------------------------------------------------------
// K4: batched LoRA stage 2 + epilogue (4 jobs in one launch)
// ---------------------------------------------------------------------------
struct Stage2Job  { const float* U; const float* V2; const float* bias;
                    float* out; const float* e1; const float* e2; int D; int mode; };
struct Stage2Jobs { Stage2Job j[4]; };

__global__ __launch_bounds__(256) void stage2_all_kernel(Stage2Jobs jobs)
{
    const Stage2Job jb = jobs.j[blockIdx.z];
    const int D = jb.D, mode = jb.mode;

    constexpr int ROWS = 32;
    __shared__ float Us[ROWS][128];
    const int tid = threadIdx.x;
    const int row0 = blockIdx.y * ROWS;
    const int c = blockIdx.x * 256 + tid;

    {
        const int q = D >> 2;
        const int total = ROWS * q;
        for (int idx = tid; idx < total; idx += 256) {
            int rr = idx / q;
            int cc = (idx - rr*q) << 2;
            *(float4*)&Us[rr][cc] = *(const float4*)&jb.U[(size_t)(row0+rr)*D + cc];
        }
    }
    __syncthreads();

    float acc[ROWS];
#pragma unroll
    for (int r = 0; r < ROWS; r++) acc[r] = 0.f;

#pragma unroll 4
    for (int d0 = 0; d0 < D; d0 += 4) {
        float v0 = jb.V2[(size_t)(d0+0)*CC + c];
        float v1 = jb.V2[(size_t)(d0+1)*CC + c];
        float v2 = jb.V2[(size_t)(d0+2)*CC + c];
        float v3 = jb.V2[(size_t)(d0+3)*CC + c];
#pragma unroll
        for (int r = 0; r < ROWS; r++) {
            float4 u = *(const float4*)&Us[r][d0];
            acc[r] += u.x*v0 + u.y*v1 + u.z*v2 + u.w*v3;
        }
    }
    float bv = (mode == 3) ? 0.f : jb.bias[c];
#pragma unroll
    for (int r = 0; r < ROWS; r++) {
        size_t idx = (size_t)(row0+r)*CC + c;
        float y = acc[r] + bv;
        if (mode == 0)      jb.out[idx] = 0.6065306597126334f * (1.f/(1.f+expf(-y)));
        else if (mode == 1) jb.out[idx] = 1.f/(1.f+expf(-y));
        else if (mode == 2) {
            float s = 1.f/(1.f+expf(-y));
            float vr = jb.e1[idx];
            jb.out[idx] = vr + (jb.e2[idx]-vr)*s;
        } else              jb.out[idx] = y;
    }
}

// ---------------------------------------------------------------------------
// K5: per-(b,t,h) prep + per-step scalars br = <bw,r>, kr = <kf,r>
// ---------------------------------------------------------------------------
__global__ __launch_bounds__(256) void prep_kernel(
    const float* __restrict__ k, const float* __restrict__ r,
    const float* __restrict__ asig,
    const float* __restrict__ kkvec, const float* __restrict__ kavec,
    float* __restrict__ aw, float* __restrict__ bw, float* __restrict__ kf,
    float* __restrict__ brg, float* __restrict__ krg)
{
    const int tid = threadIdx.x;
    const int g = tid >> 6, n = tid & 63;
    const size_t head = (size_t)blockIdx.x*4 + g;
    const size_t idx = head*64 + n;
    const int c = (int)(idx & (CC-1));

    float kv = k[idx];
    float kk = kv * kkvec[c];
    float ss = kk*kk;
#pragma unroll
    for (int off=16; off; off>>=1) ss += __shfl_xor_sync(0xffffffffu, ss, off);
    __shared__ float red[8];
    if ((tid & 31)==0) red[tid>>5] = ss;
    __syncthreads();
    float tot = red[g*2] + red[g*2+1];
    float inv = 1.f / fmaxf(sqrtf(tot), 1e-12f);
    float kkn = kk * inv;
    float a = asig[idx];
    float awv = -kkn;
    float bwv = kkn * a;
    float kfv = kv + kavec[c]*(kv*a - kv);
    aw[idx] = awv;
    bw[idx] = bwv;
    kf[idx] = kfv;

    // phase 2: per-step scalars
    float rv = r[idx];
    float s1 = bwv*rv, s2 = kfv*rv;
#pragma unroll
    for (int off=16; off; off>>=1){
        s1 += __shfl_xor_sync(0xffffffffu, s1, off);
        s2 += __shfl_xor_sync(0xffffffffu, s2, off);
    }
    __shared__ float red2[8][2];
    if ((tid & 31)==0){ int w = tid>>5; red2[w][0]=s1; red2[w][1]=s2; }
    __syncthreads();
    if (n == 0) {
        float BR = red2[g*2][0] + red2[g*2+1][0];
        float KR = red2[g*2][1] + red2[g*2+1][1];
        int row = (int)(head >> 5);        // bt
        int hh  = (int)(head & 31);
        int bb  = row >> 10, t = row & (TT-1);
        size_t off2 = ((size_t)bb*HH + hh)*TT + t;
        brg[off2] = BR;
        krg[off2] = KR;
    }
}

// ---------------------------------------------------------------------------
// K6: WKV7 recurrence, v-split x4 + o-decomposition.
//     o_t = S_{t-1}.(d*r) + sa*<b,r> + v*<k,r>  (scalars precomputed in prep)
//     Block = (b,h,vq): 16 v-rows. 128 threads: thread=(v-row, k-eighth), S[8].
// ---------------------------------------------------------------------------
__global__ __launch_bounds__(128) void wkv_kernel(
    const float* __restrict__ r, const float* __restrict__ k,
    const float* __restrict__ v, const float* __restrict__ d,
    const float* __restrict__ aw, const float* __restrict__ bw,
    const float* __restrict__ brg, const float* __restrict__ krg,
    const float* __restrict__ s0, float* __restrict__ o)
{
    const int blk = blockIdx.x;           // 0..255
    const int bh = blk >> 2;              // 0..63
    const int vq = blk & 3;
    const int b = bh >> 5, hh = bh & 31;
    const int tid = threadIdx.x;
    const int vr = tid >> 3;              // 0..15
    const int kt = tid & 7;
    const int koff = kt * 8;
    const int vg = vq*16 + vr;            // global v-row
    const int n = tid & 63;

    float S[8];
    {
        const float* sp = s0 + ((size_t)bh*64 + vg)*64 + koff;
#pragma unroll
        for (int i=0;i<8;i++) S[i] = sp[i];
    }

    __shared__ float sh[2][6][64];        // 0=r 1=k 2=v 3=d 4=aw 5=bw
    const size_t rowbase = (size_t)b*TT*CC + hh*64;
    const float* brp = brg + ((size_t)b*HH + hh)*TT;
    const float* krp = krg + ((size_t)b*HH + hh)*TT;

    float p0, p1, p2;
    {
        size_t idx = rowbase + n;
        if (tid < 64) { sh[0][0][n]=r[idx]; sh[0][1][n]=k[idx]; sh[0][2][n]=v[idx]; }
        else          { sh[0][3][n]=d[idx]; sh[0][4][n]=aw[idx]; sh[0][5][n]=bw[idx]; }
    }
    {
        size_t idx = rowbase + (size_t)1*CC + n;
        if (tid < 64) { p0=r[idx]; p1=k[idx]; p2=v[idx]; }
        else          { p0=d[idx]; p1=aw[idx]; p2=bw[idx]; }
    }
    float cbr = brp[0], ckr = krp[0];
    float nbr = brp[1], nkr = krp[1];
    __syncthreads();

    for (int t = 0; t < TT; t++) {
        const int buf = t & 1;
        if (t+1 < TT) {
            if (tid < 64) { sh[buf^1][0][n]=p0; sh[buf^1][1][n]=p1; sh[buf^1][2][n]=p2; }
            else          { sh[buf^1][3][n]=p0; sh[buf^1][4][n]=p1; sh[buf^1][5][n]=p2; }
        }
        if (t+2 < TT) {
            size_t idx = rowbase + (size_t)(t+2)*CC + n;
            if (tid < 64) { p0=r[idx]; p1=k[idx]; p2=v[idx]; }
            else          { p0=d[idx]; p1=aw[idx]; p2=bw[idx]; }
        }

        const float* shr = sh[buf][0];
        const float* shk = sh[buf][1];
        const float* shv = sh[buf][2];
        const float* shd = sh[buf][3];
        const float* sha = sh[buf][4];
        const float* shb = sh[buf][5];

        // load my 8-element slices
        float4 a40 = *(const float4*)&sha[koff];
        float4 a41 = *(const float4*)&sha[koff+4];
        float4 d40 = *(const float4*)&shd[koff];
        float4 d41 = *(const float4*)&shd[koff+4];
        float4 r40 = *(const float4*)&shr[koff];
        float4 r41 = *(const float4*)&shr[koff+4];

        // reductions: sa = sum S*a ; sd = sum S*(d*r)
        float sa0, sa1, sd0, sd1;
        sa0 = S[0]*a40.x;           sa1 = S[1]*a40.y;
        sa0 += S[2]*a40.z;          sa1 += S[3]*a40.w;
        sa0 += S[4]*a41.x;          sa1 += S[5]*a41.y;
        sa0 += S[6]*a41.z;          sa1 += S[7]*a41.w;
        sd0 = S[0]*(d40.x*r40.x);   sd1 = S[1]*(d40.y*r40.y);
        sd0 += S[2]*(d40.z*r40.z);  sd1 += S[3]*(d40.w*r40.w);
        sd0 += S[4]*(d41.x*r41.x);  sd1 += S[5]*(d41.y*r41.y);
        sd0 += S[6]*(d41.z*r41.z);  sd1 += S[7]*(d41.w*r41.w);
        float sa = sa0 + sa1;
        float sd = sd0 + sd1;
        sa += __shfl_xor_sync(0xffffffffu, sa, 1);
        sd += __shfl_xor_sync(0xffffffffu, sd, 1);
        sa += __shfl_xor_sync(0xffffffffu, sa, 2);
        sd += __shfl_xor_sync(0xffffffffu, sd, 2);
        sa += __shfl_xor_sync(0xffffffffu, sa, 4);
        sd += __shfl_xor_sync(0xffffffffu, sd, 4);

        const float vt = shv[vg];
        if (kt == 0)
            o[rowbase + (size_t)t*CC + vg] = sd + sa*cbr + vt*ckr;

        // S update
        float4 b40 = *(const float4*)&shb[koff];
        float4 b41 = *(const float4*)&shb[koff+4];
        float4 k40 = *(const float4*)&shk[koff];
        float4 k41 = *(const float4*)&shk[koff+4];
        S[0] = S[0]*d40.x + sa*b40.x + vt*k40.x;
        S[1] = S[1]*d40.y + sa*b40.y + vt*k40.y;
        S[2] = S[2]*d40.z + sa*b40.z + vt*k40.z;
        S[3] = S[3]*d40.w + sa*b40.w + vt*k40.w;
        S[4] = S[4]*d41.x + sa*b41.x + vt*k41.x;
        S[5] = S[5]*d41.y + sa*b41.y + vt*k41.y;
        S[6] = S[6]*d41.z + sa*b41.z + vt*k41.z;
        S[7] = S[7]*d41.w + sa*b41.w + vt*k41.w;

        cbr = nbr; ckr = nkr;
        if (t+2 < TT) { nbr = brp[t+2]; nkr = krp[t+2]; }
        __syncthreads();
    }
}

// ---------------------------------------------------------------------------
// K7: group norm + per-head bonus + gate multiply -> bf16 hi/lo
// ---------------------------------------------------------------------------
__global__ __launch_bounds__(256) void gn_kernel(
    const float* __restrict__ o, const float* __restrict__ r,
    const float* __restrict__ kf, const float* __restrict__ vf,
    const float* __restrict__ gg, const float* __restrict__ rk,
    const float* __restrict__ gnw, const float* __restrict__ gnb,
    __nv_bfloat16* __restrict__ xoh, __nv_bfloat16* __restrict__ xol)
{
    const int tid = threadIdx.x;
    const int g = tid >> 6, n = tid & 63;
    const size_t head = (size_t)blockIdx.x*4 + g;
    const int h = (int)(head & (HH-1));
    const size_t idx = head*64 + n;
    const int c = h*64 + n;

    float ov = o[idx];
    float rv = r[idx], kv = kf[idx];
    float s1 = ov, s2 = ov*ov, s3 = rv*kv*rk[c];
#pragma unroll
    for (int off=16; off; off>>=1){
        s1 += __shfl_xor_sync(0xffffffffu, s1, off);
        s2 += __shfl_xor_sync(0xffffffffu, s2, off);
        s3 += __shfl_xor_sync(0xffffffffu, s3, off);
    }
    __shared__ float red[8][3];
    if ((tid & 31)==0){ int w = tid>>5; red[w][0]=s1; red[w][1]=s2; red[w][2]=s3; }
    __syncthreads();
    float S1 = red[g*2][0]+red[g*2+1][0];
    float S2 = red[g*2][1]+red[g*2+1][1];
    float S3 = red[g*2][2]+red[g*2+1][2];
    float mu = S1*(1.f/64.f);
    float var = S2*(1.f/64.f) - mu*mu;
    float y = (ov-mu)*rsqrtf(var + 6.4e-4f)*gnw[c] + gnb[c] + S3*vf[idx];
    float xo = y * gg[idx];
    __nv_bfloat16 hv, lv;
    split_hilo(xo, hv, lv);
    xoh[idx] = hv;
    xol[idx] = lv;
}

// ---------------------------------------------------------------------------
// Launch
// ---------------------------------------------------------------------------
extern "C" void kernel_launch(void* const* d_in, const int* in_sizes, int n_in,
                              void* d_out, int out_size)
{
    const float* h      = (const float*)d_in[0];
    const float* shift  = (const float*)d_in[1];
    const float* s0     = (const float*)d_in[2];
    const float* vfirst = (const float*)d_in[3];
    const float* x_r = (const float*)d_in[4];
    const float* x_w = (const float*)d_in[5];
    const float* x_k = (const float*)d_in[6];
    const float* x_v = (const float*)d_in[7];
    const float* x_a = (const float*)d_in[8];
    const float* x_g = (const float*)d_in[9];
    const float* w0 = (const float*)d_in[10];
    const float* w1 = (const float*)d_in[11];
    const float* w2 = (const float*)d_in[12];
    const float* a0 = (const float*)d_in[13];
    const float* a1 = (const float*)d_in[14];
    const float* a2 = (const float*)d_in[15];
    const float* v0 = (const float*)d_in[16];
    const float* v1 = (const float*)d_in[17];
    const float* v2 = (const float*)d_in[18];
    const float* g1 = (const float*)d_in[19];
    const float* g2 = (const float*)d_in[20];
    const float* k_k = (const float*)d_in[21];
    const float* k_a = (const float*)d_in[22];
    const float* r_k = (const float*)d_in[23];
    const float* W_r = (const float*)d_in[24];
    const float* W_k = (const float*)d_in[25];
    const float* W_v = (const float*)d_in[26];
    const float* W_o = (const float*)d_in[27];
    const float* gnw = (const float*)d_in[28];
    const float* gnb = (const float*)d_in[29];
    float* out = (float*)d_out;

    float* S = nullptr;
    cudaGetSymbolAddress((void**)&S, g_scratch);

    float* xw    = S + (size_t)S_XW*BTC;
    float* xa    = S + (size_t)S_XA*BTC;
    float* xv    = S + (size_t)S_XV*BTC;
    float* xg    = S + (size_t)S_XG*BTC;
    float* rb    = S + (size_t)S_R*BTC;
    float* kb    = S + (size_t)S_K*BTC;
    float* vb    = S + (size_t)S_V*BTC;
    float* decay = S + (size_t)S_DECAY*BTC;
    float* asig  = S + (size_t)S_ASIG*BTC;
    float* gbuf  = S + (size_t)S_G*BTC;
    float* awb   = S + (size_t)S_AW*BTC;
    float* bwb   = S + (size_t)S_BW*BTC;
    float* kfb   = S + (size_t)S_KF*BTC;
    float* vfb   = S + (size_t)S_VF*BTC;
    float* ob    = S + (size_t)S_O*BTC;

    __nv_bfloat16* bfb = (__nv_bfloat16*)(S + BF16_BASE);
#define BF(i) (bfb + (size_t)(i)*BTC)
    __nv_bfloat16 *xrh=BF(B_XRH), *xrl=BF(B_XRL), *xkh=BF(B_XKH), *xkl=BF(B_XKL);
    __nv_bfloat16 *xvh=BF(B_XVH), *xvl=BF(B_XVL), *xoh=BF(B_XOH), *xol=BF(B_XOL);
    __nv_bfloat16 *wrh=BF(B_WRH), *wrl=BF(B_WRL), *wkh=BF(B_WKH), *wkl=BF(B_WKL);
    __nv_bfloat16 *wvh=BF(B_WVH), *wvl=BF(B_WVL), *woh=BF(B_WOH), *wol=BF(B_WOL);
#undef BF
    float* Uw = S + U_W_OFF;  float* Ua = S + U_A_OFF;
    float* Uv = S + U_V_OFF;  float* Ug = S + U_G_OFF;
    float* brg = S + BR_OFF;  float* krg = S + KR_OFF;

    cudaFuncSetAttribute(gemm_bf16x3,
                         cudaFuncAttributeMaxDynamicSharedMemorySize, GEMM_SMEM);

    // 0. weight conversions (one batched launch)
    CvtJobs cj;
    cj.x[0]=W_r; cj.hi[0]=wrh; cj.lo[0]=wrl;
    cj.x[1]=W_k; cj.hi[1]=wkh; cj.lo[1]=wkl;
    cj.x[2]=W_v; cj.hi[2]=wvh; cj.lo[2]=wvl;
    cj.x[3]=W_o; cj.hi[3]=woh; cj.lo[3]=wol;
    cvt_all_kernel<<<dim3(4096, 4), 256>>>(cj);

    // 1. token shift + mixes
    mix_kernel<<<4096, 256>>>(h, shift, x_r, x_w, x_k, x_v, x_a, x_g,
                              xrh, xrl, xw, xkh, xkl, xv, xvh, xvl, xa, xg);

    // 2. big r/k/v projections (batched HMMA launch, 3 jobs)
    GemmJobs gj;
    gj.j[0] = { xrh, xrl, wrh, wrl, rb };
    gj.j[1] = { xkh, xkl, wkh, wkl, kb };
    gj.j[2] = { xvh, xvl, wvh, wvl, vb };
    gemm_bf16x3<<<dim3(8, 16, 3), 256, GEMM_SMEM>>>(gj);

    // 3. LoRA stage 1 (batched, 5 column-tile jobs, 64x64 register tiling)
    Lora1Jobs lj;
    lj.j[0] = { xw, w1, Uw,  64, 0, 1 };   // tanh
    lj.j[1] = { xa, a1, Ua,  64, 0, 0 };
    lj.j[2] = { xv, v1, Uv,  32, 0, 0 };
    lj.j[3] = { xg, g1, Ug, 128, 0, 2 };   // sigmoid
    lj.j[4] = { xg, g1, Ug, 128, 64, 2 };  // sigmoid (cols 64..127)
    lora1_all_kernel<<<dim3(32, 5), 256>>>(lj);

    // 4. LoRA stage 2 + epilogues (batched, 4 jobs)
    Stage2Jobs sj;
    sj.j[0] = { Uw, w2, w0, decay, nullptr, nullptr,  64, 0 };
    sj.j[1] = { Ua, a2, a0, asig,  nullptr, nullptr,  64, 1 };
    sj.j[2] = { Uv, v2, v0, vfb,   vb,      vfirst,   32, 2 };
    sj.j[3] = { Ug, g2, nullptr, gbuf, nullptr, nullptr, 128, 3 };
    stage2_all_kernel<<<dim3(8, 64, 4), 256>>>(sj);

    // 5. kk-normalize / k lerp prep + per-step scalars
    prep_kernel<<<BT*HH/4, 256>>>(kb, rb, asig, k_k, k_a, awb, bwb, kfb, brg, krg);

    // 6. WKV7 recurrence (v-split x4: 256 blocks, o-decomposition)
    wkv_kernel<<<BB*HH*4, 128>>>(rb, kfb, vfb, decay, awb, bwb, brg, krg, s0, ob);

    // 7. group norm + bonus + gate
    gn_kernel<<<BT*HH/4, 256>>>(ob, rb, kfb, vfb, gbuf, r_k, gnw, gnb, xoh, xol);

    // 8. output projection (single job)
    GemmJobs oj;
    oj.j[0] = { xoh, xol, woh, wol, out };
    oj.j[1] = oj.j[0];
    oj.j[2] = oj.j[0];
    gemm_bf16x3<<<dim3(8, 16, 1), 256, GEMM_SMEM>>>(oj);
}

// round 7
// speedup vs baseline: 2.3047x; 1.3050x over previous
#include <cuda_runtime.h>
#include <cuda_bf16.h>
#include <math.h>
#include <cstdint>

// Problem constants
#define BB 2
#define TT 1024
#define CC 2048
#define HH 32
#define NN 64
#define BT (BB*TT)              // 2048
#define BTC (BB*TT*CC)          // 4194304  (== CC*CC)

// ---------------------------------------------------------------------------
// Scratch (static device memory)
// ---------------------------------------------------------------------------
enum { S_XW=0, S_XA, S_XV, S_XG, S_R, S_K, S_V,
       S_DECAY, S_ASIG, S_G, S_AW, S_BW, S_KF, S_VF, S_O, N_F32 };
enum { B_XRH=0, B_XRL, B_XKH, B_XKL, B_XVH, B_XVL, B_XOH, B_XOL,
       B_WRH, B_WRL, B_WKH, B_WKL, B_WVH, B_WVL, B_WOH, B_WOL, N_BF16 };
#define BF16_BASE ((size_t)N_F32*BTC)                 // in floats
#define U_W_OFF   (BF16_BASE + (size_t)N_BF16*BTC/2)
#define U_A_OFF   (U_W_OFF + (size_t)BT*64)
#define U_V_OFF   (U_A_OFF + (size_t)BT*64)
#define U_G_OFF   (U_V_OFF + (size_t)BT*32)
#define BR_OFF    (U_G_OFF + (size_t)BT*128)
#define KR_OFF    (BR_OFF + (size_t)BB*HH*TT)
#define SCRATCH_FLOATS (KR_OFF + (size_t)BB*HH*TT)

__device__ float g_scratch[SCRATCH_FLOATS];

// ---------------------------------------------------------------------------
// PTX helpers (plain sm_103-compatible)
// ---------------------------------------------------------------------------
__device__ __forceinline__ uint32_t smem_u32(const void* p) {
    uint32_t a;
    asm("{ .reg .u64 t; cvta.to.shared.u64 t, %1; cvt.u32.u64 %0, t; }" : "=r"(a) : "l"(p));
    return a;
}
#define CP16(dst, src) \
    asm volatile("cp.async.cg.shared.global [%0], [%1], 16;" :: "r"(dst), "l"(src))
#define CP4(dst, src) \
    asm volatile("cp.async.ca.shared.global [%0], [%1], 4;" :: "r"(dst), "l"(src))
#define CP_COMMIT() asm volatile("cp.async.commit_group;" ::: "memory")
#define CP_WAIT2()  asm volatile("cp.async.wait_group 2;"  ::: "memory")
#define LDSM4(r, addr) \
    asm volatile("ldmatrix.sync.aligned.m8n8.x4.shared.b16 {%0,%1,%2,%3}, [%4];" \
        : "=r"((r)[0]), "=r"((r)[1]), "=r"((r)[2]), "=r"((r)[3]) : "r"(addr))
#define MMA16816(d, a, b0, b1) \
    asm volatile("mma.sync.aligned.m16n8k16.row.col.f32.bf16.bf16.f32 " \
        "{%0,%1,%2,%3}, {%4,%5,%6,%7}, {%8,%9}, {%0,%1,%2,%3};" \
        : "+f"((d)[0]), "+f"((d)[1]), "+f"((d)[2]), "+f"((d)[3]) \
        : "r"((a)[0]), "r"((a)[1]), "r"((a)[2]), "r"((a)[3]), "r"(b0), "r"(b1))

// ---------------------------------------------------------------------------
// hi/lo split helpers
// ---------------------------------------------------------------------------
__device__ __forceinline__ void split_hilo(float v, __nv_bfloat16& h, __nv_bfloat16& l) {
    h = __float2bfloat16(v);
    l = __float2bfloat16(v - __bfloat162float(h));
}
__device__ __forceinline__ void store_hilo4(__nv_bfloat16* hi, __nv_bfloat16* lo,
                                            size_t off, float4 v) {
    __nv_bfloat16 hv[4], lv[4];
    split_hilo(v.x, hv[0], lv[0]); split_hilo(v.y, hv[1], lv[1]);
    split_hilo(v.z, hv[2], lv[2]); split_hilo(v.w, hv[3], lv[3]);
    *(uint2*)&hi[off] = *(uint2*)hv;
    *(uint2*)&lo[off] = *(uint2*)lv;
}

// ---------------------------------------------------------------------------
// K0: batched fp32 -> bf16 hi/lo conversion (4 weights in one launch)
// ---------------------------------------------------------------------------
struct CvtJobs { const float* x[4]; __nv_bfloat16* hi[4]; __nv_bfloat16* lo[4]; };

__global__ __launch_bounds__(256) void cvt_all_kernel(CvtJobs jobs)
{
    const int z = blockIdx.y;
    size_t i = ((size_t)blockIdx.x * 256 + threadIdx.x) * 4;
    float4 v = *(const float4*)&jobs.x[z][i];
    store_hilo4(jobs.hi[z], jobs.lo[z], i, v);
}

// ---------------------------------------------------------------------------
// K1: token shift + 6-way mix
// ---------------------------------------------------------------------------
__global__ __launch_bounds__(256) void mix_kernel(
    const float* __restrict__ h, const float* __restrict__ shift,
    const float* __restrict__ mr, const float* __restrict__ mw,
    const float* __restrict__ mk, const float* __restrict__ mv,
    const float* __restrict__ ma, const float* __restrict__ mg,
    __nv_bfloat16* __restrict__ xrh, __nv_bfloat16* __restrict__ xrl,
    float* __restrict__ oxw,
    __nv_bfloat16* __restrict__ xkh, __nv_bfloat16* __restrict__ xkl,
    float* __restrict__ oxv,
    __nv_bfloat16* __restrict__ xvh, __nv_bfloat16* __restrict__ xvl,
    float* __restrict__ oxa, float* __restrict__ oxg)
{
    int gid = blockIdx.x * 256 + threadIdx.x;
    int row = gid >> 9;
    int c   = (gid & 511) << 2;
    int t   = row & (TT-1);
    int b   = row >> 10;
    size_t off = (size_t)row * CC + c;

    float4 hv = *(const float4*)&h[off];
    float4 pv;
    if (t == 0) pv = *(const float4*)&shift[(size_t)b*CC + c];
    else        pv = *(const float4*)&h[off - CC];
    float4 xx = make_float4(pv.x-hv.x, pv.y-hv.y, pv.z-hv.z, pv.w-hv.w);

#define MIXV(mvec, o)                                                 \
    {   float4 m = *(const float4*)&mvec[c];                          \
        o = make_float4(hv.x + xx.x*m.x, hv.y + xx.y*m.y,             \
                        hv.z + xx.z*m.z, hv.w + xx.w*m.w); }
    float4 vr; MIXV(mr, vr); store_hilo4(xrh, xrl, off, vr);
    float4 vw; MIXV(mw, vw); *(float4*)&oxw[off] = vw;
    float4 vk; MIXV(mk, vk); store_hilo4(xkh, xkl, off, vk);
    float4 vv; MIXV(mv, vv); *(float4*)&oxv[off] = vv; store_hilo4(xvh, xvl, off, vv);
    float4 va; MIXV(ma, va); *(float4*)&oxa[off] = va;
    float4 vg; MIXV(mg, vg); *(float4*)&oxg[off] = vg;
#undef MIXV
}

// ---------------------------------------------------------------------------
// K2: HMMA bf16x3 GEMM (batched over blockIdx.z jobs)
// ---------------------------------------------------------------------------
#define GSTAGES 3
#define TILE_A 8192              // 128 rows x 64 B
#define TILE_B 16384             // 256 rows x 64 B
#define STAGE_B (2*TILE_A + 2*TILE_B)   // 49152
#define GEMM_SMEM (GSTAGES*STAGE_B)     // 147456

struct GemmJob  { const __nv_bfloat16 *Ah, *Al, *Bh, *Bl; float* Y; };
struct GemmJobs { GemmJob j[3]; };

__device__ __forceinline__ uint32_t swz(uint32_t row, uint32_t chunk) {
    return row*64u + ((chunk ^ ((row >> 1) & 3u)) << 4);
}

__global__ __launch_bounds__(256, 1) void gemm_bf16x3(GemmJobs jobs)
{
    extern __shared__ char dynsmem[];
    const GemmJob gj = jobs.j[blockIdx.z];
    const __nv_bfloat16* __restrict__ Ahi = gj.Ah;
    const __nv_bfloat16* __restrict__ Alo = gj.Al;
    const __nv_bfloat16* __restrict__ Bhi = gj.Bh;
    const __nv_bfloat16* __restrict__ Blo = gj.Bl;
    float* __restrict__ Y = gj.Y;

    const uint32_t sb = smem_u32(dynsmem);
    const int tid  = threadIdx.x;
    const int lane = tid & 31;
    const int warp = tid >> 5;
    const int wm = warp >> 2;
    const int wn = warp & 3;
    const int bm = blockIdx.y << 7;
    const int bn = blockIdx.x << 8;

    auto load_stage = [&](int chunk, int stage) {
        const uint32_t st = sb + (uint32_t)stage * STAGE_B;
        const int k0 = chunk << 5;
#pragma unroll
        for (int i = 0; i < 2; i++) {
            int idx = tid + (i << 8);
            int row = idx >> 2, ch = idx & 3;
            uint32_t d = st + swz(row, ch);
            size_t g = (size_t)(bm + row) * CC + k0 + ch * 8;
            CP16(d,          Ahi + g);
            CP16(d + TILE_A, Alo + g);
        }
#pragma unroll
        for (int i = 0; i < 4; i++) {
            int idx = tid + (i << 8);
            int row = idx >> 2, ch = idx & 3;
            uint32_t d = st + 2*TILE_A + swz(row, ch);
            size_t g = (size_t)(bn + row) * CC + k0 + ch * 8;
            CP16(d,          Bhi + g);
            CP16(d + TILE_B, Blo + g);
        }
    };

    float acc[4][8][4];
#pragma unroll
    for (int mi=0;mi<4;mi++)
#pragma unroll
        for (int ni=0;ni<8;ni++)
#pragma unroll
            for (int j=0;j<4;j++) acc[mi][ni][j] = 0.f;

#pragma unroll
    for (int s = 0; s < GSTAGES; s++) { load_stage(s, s); CP_COMMIT(); }

    const int a_row = wm*64 + (lane & 7) + ((lane >> 3) & 1) * 8;
    const int a_ch  = (lane >> 4);
    const int b_row = wn*64 + (lane & 7) + (lane >> 4) * 8;
    const int b_ch  = ((lane >> 3) & 1);

    for (int it = 0; it < 64; it++) {
        const int stage = it % GSTAGES;
        const uint32_t st = sb + (uint32_t)stage * STAGE_B;
        CP_WAIT2();
        __syncthreads();

#pragma unroll
        for (int ks = 0; ks < 2; ks++) {
            uint32_t ah[4][4], al[4][4], b[4][4];
#pragma unroll
            for (int mi = 0; mi < 4; mi++) {
                uint32_t a = st + swz((uint32_t)(a_row + mi*16), (uint32_t)(a_ch + ks*2));
                LDSM4(ah[mi], a);
                LDSM4(al[mi], a + TILE_A);
            }
#pragma unroll
            for (int j = 0; j < 4; j++) {
                uint32_t baddr = st + 2*TILE_A +
                    swz((uint32_t)(b_row + j*16), (uint32_t)(b_ch + ks*2));
                LDSM4(b[j], baddr);
            }
#pragma unroll
            for (int mi = 0; mi < 4; mi++)
#pragma unroll
                for (int ni = 0; ni < 8; ni++)
                    MMA16816(acc[mi][ni], ah[mi], b[ni>>1][(ni&1)*2], b[ni>>1][(ni&1)*2+1]);
#pragma unroll
            for (int mi = 0; mi < 4; mi++)
#pragma unroll
                for (int ni = 0; ni < 8; ni++)
                    MMA16816(acc[mi][ni], al[mi], b[ni>>1][(ni&1)*2], b[ni>>1][(ni&1)*2+1]);
#pragma unroll
            for (int j = 0; j < 4; j++) {
                uint32_t baddr = st + 2*TILE_A + TILE_B +
                    swz((uint32_t)(b_row + j*16), (uint32_t)(b_ch + ks*2));
                LDSM4(b[j], baddr);
            }
#pragma unroll
            for (int mi = 0; mi < 4; mi++)
#pragma unroll
                for (int ni = 0; ni < 8; ni++)
                    MMA16816(acc[mi][ni], ah[mi], b[ni>>1][(ni&1)*2], b[ni>>1][(ni&1)*2+1]);
        }

        __syncthreads();
        if (it + GSTAGES < 64) load_stage(it + GSTAGES, stage);
        CP_COMMIT();
    }

    const int erow = bm + wm*64 + (lane >> 2);
    const int ecol = bn + wn*64 + (lane & 3) * 2;
#pragma unroll
    for (int mi = 0; mi < 4; mi++)
#pragma unroll
        for (int ni = 0; ni < 8; ni++) {
            size_t r0 = (size_t)(erow + mi*16) * CC + ecol + ni*8;
            *(float2*)&Y[r0]        = make_float2(acc[mi][ni][0], acc[mi][ni][1]);
            *(float2*)&Y[r0 + 8*CC] = make_float2(acc[mi][ni][2], acc[mi][ni][3]);
        }
}

// ---------------------------------------------------------------------------
// K3: batched LoRA stage 1 — register-tiled 64x64 block, 4x4 thread tile.
// ---------------------------------------------------------------------------
struct Lora1Job  { const float* X; const float* G; float* U; int D; int col0; int act; };
struct Lora1Jobs { Lora1Job j[5]; };

__global__ __launch_bounds__(256) void lora1_all_kernel(Lora1Jobs jobs)
{
    const Lora1Job jb = jobs.j[blockIdx.y];
    const float* __restrict__ X = jb.X;
    const float* __restrict__ G = jb.G;
    const int D = jb.D, col0 = jb.col0, act = jb.act;

    __shared__ float Xs[32][68];   // [k][row], transposed on store
    __shared__ float Gs[32][64];   // [k][col]

    const int tid = threadIdx.x;
    const int bm = blockIdx.x * 64;
    const int tx = tid & 15;       // col group
    const int ty = tid >> 4;       // row group

    float4 px[2], pg[2];
    const int xrow = tid & 63;
    const int xkc0 = (tid >> 6) << 2;
    const int gkr0 = tid >> 4;
    const int gcc  = (tid & 15) << 2;

    auto gload = [&](int k0) {
#pragma unroll
        for (int i = 0; i < 2; i++) {
            px[i] = *(const float4*)&X[(size_t)(bm + xrow)*CC + k0 + xkc0 + i*16];
            if (col0 + gcc < D)
                pg[i] = *(const float4*)&G[(size_t)(k0 + gkr0 + i*16)*D + col0 + gcc];
            else
                pg[i] = make_float4(0.f, 0.f, 0.f, 0.f);
        }
    };
    auto sstore = [&]() {
#pragma unroll
        for (int i = 0; i < 2; i++) {
            int kc = xkc0 + i*16;
            Xs[kc+0][xrow] = px[i].x; Xs[kc+1][xrow] = px[i].y;
            Xs[kc+2][xrow] = px[i].z; Xs[kc+3][xrow] = px[i].w;
            *(float4*)&Gs[gkr0 + i*16][gcc] = pg[i];
        }
    };

    float acc[4][4];
#pragma unroll
    for (int i=0;i<4;i++)
#pragma unroll
        for (int j=0;j<4;j++) acc[i][j] = 0.f;

    gload(0); sstore(); __syncthreads();

    for (int k0 = 32; k0 <= 2048; k0 += 32) {
        if (k0 < 2048) gload(k0);
#pragma unroll
        for (int kk = 0; kk < 32; kk++) {
            float4 xa = *(const float4*)&Xs[kk][ty*4];
            float4 gb = *(const float4*)&Gs[kk][tx*4];
            float xv[4] = {xa.x, xa.y, xa.z, xa.w};
            float gv[4] = {gb.x, gb.y, gb.z, gb.w};
#pragma unroll
            for (int i=0;i<4;i++)
#pragma unroll
                for (int j=0;j<4;j++)
                    acc[i][j] += xv[i]*gv[j];
        }
        __syncthreads();
        if (k0 < 2048) { sstore(); __syncthreads(); }
    }

#pragma unroll
    for (int i=0;i<4;i++) {
        int row = bm + ty*4 + i;
#pragma unroll
        for (int j=0;j<4;j++) {
            int col = col0 + tx*4 + j;
            if (col < D) {
                float y = acc[i][j];
                if (act == 1) y = tanhf(y);
                else if (act == 2) y = 1.f/(1.f+expf(-y));
                jb.U[(size_t)row*D + col] = y;
            }
        }
    }
}

// ---------------------------------------------------------------------------
// K4: batched LoRA stage 2 + epilogue (4 jobs in one launch)
// ---------------------------------------------------------------------------
struct Stage2Job  { const float* U; const float* V2; const float* bias;
                    float* out; const float* e1; const float* e2; int D; int mode; };
struct Stage2Jobs { Stage2Job j[4]; };

__global__ __launch_bounds__(256) void stage2_all_kernel(Stage2Jobs jobs)
{
    const Stage2Job jb = jobs.j[blockIdx.z];
    const int D = jb.D, mode = jb.mode;

    constexpr int ROWS = 32;
    __shared__ float Us[ROWS][128];
    const int tid = threadIdx.x;
    const int row0 = blockIdx.y * ROWS;
    const int c = blockIdx.x * 256 + tid;

    {
        const int q = D >> 2;
        const int total = ROWS * q;
        for (int idx = tid; idx < total; idx += 256) {
            int rr = idx / q;
            int cc = (idx - rr*q) << 2;
            *(float4*)&Us[rr][cc] = *(const float4*)&jb.U[(size_t)(row0+rr)*D + cc];
        }
    }
    __syncthreads();

    float acc[ROWS];
#pragma unroll
    for (int r = 0; r < ROWS; r++) acc[r] = 0.f;

#pragma unroll 4
    for (int d0 = 0; d0 < D; d0 += 4) {
        float v0 = jb.V2[(size_t)(d0+0)*CC + c];
        float v1 = jb.V2[(size_t)(d0+1)*CC + c];
        float v2 = jb.V2[(size_t)(d0+2)*CC + c];
        float v3 = jb.V2[(size_t)(d0+3)*CC + c];
#pragma unroll
        for (int r = 0; r < ROWS; r++) {
            float4 u = *(const float4*)&Us[r][d0];
            acc[r] += u.x*v0 + u.y*v1 + u.z*v2 + u.w*v3;
        }
    }
    float bv = (mode == 3) ? 0.f : jb.bias[c];
#pragma unroll
    for (int r = 0; r < ROWS; r++) {
        size_t idx = (size_t)(row0+r)*CC + c;
        float y = acc[r] + bv;
        if (mode == 0)      jb.out[idx] = 0.6065306597126334f * (1.f/(1.f+expf(-y)));
        else if (mode == 1) jb.out[idx] = 1.f/(1.f+expf(-y));
        else if (mode == 2) {
            float s = 1.f/(1.f+expf(-y));
            float vr = jb.e1[idx];
            jb.out[idx] = vr + (jb.e2[idx]-vr)*s;
        } else              jb.out[idx] = y;
    }
}

// ---------------------------------------------------------------------------
// K5: per-(b,t,h) prep + per-step scalars br = <bw,r>, kr = <kf,r>
// ---------------------------------------------------------------------------
__global__ __launch_bounds__(256) void prep_kernel(
    const float* __restrict__ k, const float* __restrict__ r,
    const float* __restrict__ asig,
    const float* __restrict__ kkvec, const float* __restrict__ kavec,
    float* __restrict__ aw, float* __restrict__ bw, float* __restrict__ kf,
    float* __restrict__ brg, float* __restrict__ krg)
{
    const int tid = threadIdx.x;
    const int g = tid >> 6, n = tid & 63;
    const size_t head = (size_t)blockIdx.x*4 + g;
    const size_t idx = head*64 + n;
    const int c = (int)(idx & (CC-1));

    float kv = k[idx];
    float kk = kv * kkvec[c];
    float ss = kk*kk;
#pragma unroll
    for (int off=16; off; off>>=1) ss += __shfl_xor_sync(0xffffffffu, ss, off);
    __shared__ float red[8];
    if ((tid & 31)==0) red[tid>>5] = ss;
    __syncthreads();
    float tot = red[g*2] + red[g*2+1];
    float inv = 1.f / fmaxf(sqrtf(tot), 1e-12f);
    float kkn = kk * inv;
    float a = asig[idx];
    float awv = -kkn;
    float bwv = kkn * a;
    float kfv = kv + kavec[c]*(kv*a - kv);
    aw[idx] = awv;
    bw[idx] = bwv;
    kf[idx] = kfv;

    // phase 2: per-step scalars
    float rv = r[idx];
    float s1 = bwv*rv, s2 = kfv*rv;
#pragma unroll
    for (int off=16; off; off>>=1){
        s1 += __shfl_xor_sync(0xffffffffu, s1, off);
        s2 += __shfl_xor_sync(0xffffffffu, s2, off);
    }
    __shared__ float red2[8][2];
    if ((tid & 31)==0){ int w = tid>>5; red2[w][0]=s1; red2[w][1]=s2; }
    __syncthreads();
    if (n == 0) {
        float BR = red2[g*2][0] + red2[g*2+1][0];
        float KR = red2[g*2][1] + red2[g*2+1][1];
        int row = (int)(head >> 5);        // bt
        int hh  = (int)(head & 31);
        int bb  = row >> 10, t = row & (TT-1);
        size_t off2 = ((size_t)bb*HH + hh)*TT + t;
        brg[off2] = BR;
        krg[off2] = KR;
    }
}

// ---------------------------------------------------------------------------
// K6: WKV7 recurrence, v-split x4, cp.async 6-deep ring buffer.
//     o_t = S_{t-1}.(d*r) + sa*<b,r> + v*<k,r>  (scalars in smem tables)
// ---------------------------------------------------------------------------
#define PF 6

__global__ __launch_bounds__(128) void wkv_kernel(
    const float* __restrict__ r, const float* __restrict__ k,
    const float* __restrict__ v, const float* __restrict__ d,
    const float* __restrict__ aw, const float* __restrict__ bw,
    const float* __restrict__ brg, const float* __restrict__ krg,
    const float* __restrict__ s0, float* __restrict__ o)
{
    const int blk = blockIdx.x;           // 0..255
    const int bh = blk >> 2;              // 0..63
    const int vq = blk & 3;
    const int b = bh >> 5, hh = bh & 31;
    const int tid = threadIdx.x;
    const int vr = tid >> 3;              // 0..15
    const int kt = tid & 7;
    const int koff = kt * 8;
    const int vg = vq*16 + vr;            // global v-row

    __shared__ float ring[PF][6][64];     // [buf][arr][n]; arr: 0=r 1=k 2=v 3=d 4=aw 5=bw
    __shared__ float brs[TT], krs[TT];

    const size_t rowbase = (size_t)b*TT*CC + hh*64;
    const uint32_t ring0 = smem_u32(ring);

    // per-thread cp.async mapping: 3 of the 384 elements per step
    const float* srcb[3];
    uint32_t dsto[3];
#pragma unroll
    for (int j = 0; j < 3; j++) {
        int e = tid + j*128;
        int arr = e >> 6, n = e & 63;
        const float* bp = (arr==0) ? r : (arr==1) ? k : (arr==2) ? v :
                          (arr==3) ? d : (arr==4) ? aw : bw;
        srcb[j] = bp + rowbase + n;
        dsto[j] = (uint32_t)(arr*64 + n) * 4u;
    }

    // load br/kr scalar tables into smem (one-time)
    {
        const float* brp = brg + ((size_t)b*HH + hh)*TT;
        const float* krp = krg + ((size_t)b*HH + hh)*TT;
        for (int i = tid; i < TT; i += 128) { brs[i] = brp[i]; krs[i] = krp[i]; }
    }

    // state
    float S[8];
    {
        const float* sp = s0 + ((size_t)bh*64 + vg)*64 + koff;
#pragma unroll
        for (int i=0;i<8;i++) S[i] = sp[i];
    }

    // prologue: prefetch steps 0..PF-2 (one commit group each)
#pragma unroll
    for (int s = 0; s < PF-1; s++) {
        uint32_t dbase = ring0 + (uint32_t)s * (6*64*4);
#pragma unroll
        for (int j = 0; j < 3; j++)
            CP4(dbase + dsto[j], srcb[j] + (size_t)s*CC);
        CP_COMMIT();
    }

    int buf = 0;
    for (int t = 0; t < TT; t++) {
        // group for step t complete when <= PF-2 groups outstanding
        asm volatile("cp.async.wait_group %0;" :: "n"(PF-2) : "memory");
        __syncthreads();

        // issue prefetch for step t+PF-1 into buffer (buf-1+PF)%PF (freed by step t-1)
        {
            const int ts = t + PF - 1;
            int pbuf = buf - 1; if (pbuf < 0) pbuf += PF;
            if (ts < TT) {
                uint32_t dbase = ring0 + (uint32_t)pbuf * (6*64*4);
#pragma unroll
                for (int j = 0; j < 3; j++)
                    CP4(dbase + dsto[j], srcb[j] + (size_t)ts*CC);
            }
            CP_COMMIT();   // commit even when empty to keep group count uniform
        }

        const float* shr = ring[buf][0];
        const float* shk = ring[buf][1];
        const float* shv = ring[buf][2];
        const float* shd = ring[buf][3];
        const float* sha = ring[buf][4];
        const float* shb = ring[buf][5];

        float4 a40 = *(const float4*)&sha[koff];
        float4 a41 = *(const float4*)&sha[koff+4];
        float4 d40 = *(const float4*)&shd[koff];
        float4 d41 = *(const float4*)&shd[koff+4];
        float4 r40 = *(const float4*)&shr[koff];
        float4 r41 = *(const float4*)&shr[koff+4];

        // reductions: sa = sum S*a ; sd = sum S*(d*r)
        float sa0, sa1, sd0, sd1;
        sa0 = S[0]*a40.x;           sa1 = S[1]*a40.y;
        sa0 += S[2]*a40.z;          sa1 += S[3]*a40.w;
        sa0 += S[4]*a41.x;          sa1 += S[5]*a41.y;
        sa0 += S[6]*a41.z;          sa1 += S[7]*a41.w;
        sd0 = S[0]*(d40.x*r40.x);   sd1 = S[1]*(d40.y*r40.y);
        sd0 += S[2]*(d40.z*r40.z);  sd1 += S[3]*(d40.w*r40.w);
        sd0 += S[4]*(d41.x*r41.x);  sd1 += S[5]*(d41.y*r41.y);
        sd0 += S[6]*(d41.z*r41.z);  sd1 += S[7]*(d41.w*r41.w);
        float sa = sa0 + sa1;
        float sd = sd0 + sd1;
        sa += __shfl_xor_sync(0xffffffffu, sa, 1);
        sd += __shfl_xor_sync(0xffffffffu, sd, 1);
        sa += __shfl_xor_sync(0xffffffffu, sa, 2);
        sd += __shfl_xor_sync(0xffffffffu, sd, 2);
        sa += __shfl_xor_sync(0xffffffffu, sa, 4);
        sd += __shfl_xor_sync(0xffffffffu, sd, 4);

        const float vt = shv[vg];
        if (kt == 0)
            o[rowbase + (size_t)t*CC + vg] = sd + sa*brs[t] + vt*krs[t];

        // S update
        float4 b40 = *(const float4*)&shb[koff];
        float4 b41 = *(const float4*)&shb[koff+4];
        float4 k40 = *(const float4*)&shk[koff];
        float4 k41 = *(const float4*)&shk[koff+4];
        S[0] = S[0]*d40.x + sa*b40.x + vt*k40.x;
        S[1] = S[1]*d40.y + sa*b40.y + vt*k40.y;
        S[2] = S[2]*d40.z + sa*b40.z + vt*k40.z;
        S[3] = S[3]*d40.w + sa*b40.w + vt*k40.w;
        S[4] = S[4]*d41.x + sa*b41.x + vt*k41.x;
        S[5] = S[5]*d41.y + sa*b41.y + vt*k41.y;
        S[6] = S[6]*d41.z + sa*b41.z + vt*k41.z;
        S[7] = S[7]*d41.w + sa*b41.w + vt*k41.w;

        buf++; if (buf == PF) buf = 0;
    }
}

// ---------------------------------------------------------------------------
// K7: group norm + per-head bonus + gate multiply -> bf16 hi/lo
// ---------------------------------------------------------------------------
__global__ __launch_bounds__(256) void gn_kernel(
    const float* __restrict__ o, const float* __restrict__ r,
    const float* __restrict__ kf, const float* __restrict__ vf,
    const float* __restrict__ gg, const float* __restrict__ rk,
    const float* __restrict__ gnw, const float* __restrict__ gnb,
    __nv_bfloat16* __restrict__ xoh, __nv_bfloat16* __restrict__ xol)
{
    const int tid = threadIdx.x;
    const int g = tid >> 6, n = tid & 63;
    const size_t head = (size_t)blockIdx.x*4 + g;
    const int h = (int)(head & (HH-1));
    const size_t idx = head*64 + n;
    const int c = h*64 + n;

    float ov = o[idx];
    float rv = r[idx], kv = kf[idx];
    float s1 = ov, s2 = ov*ov, s3 = rv*kv*rk[c];
#pragma unroll
    for (int off=16; off; off>>=1){
        s1 += __shfl_xor_sync(0xffffffffu, s1, off);
        s2 += __shfl_xor_sync(0xffffffffu, s2, off);
        s3 += __shfl_xor_sync(0xffffffffu, s3, off);
    }
    __shared__ float red[8][3];
    if ((tid & 31)==0){ int w = tid>>5; red[w][0]=s1; red[w][1]=s2; red[w][2]=s3; }
    __syncthreads();
    float S1 = red[g*2][0]+red[g*2+1][0];
    float S2 = red[g*2][1]+red[g*2+1][1];
    float S3 = red[g*2][2]+red[g*2+1][2];
    float mu = S1*(1.f/64.f);
    float var = S2*(1.f/64.f) - mu*mu;
    float y = (ov-mu)*rsqrtf(var + 6.4e-4f)*gnw[c] + gnb[c] + S3*vf[idx];
    float xo = y * gg[idx];
    __nv_bfloat16 hv, lv;
    split_hilo(xo, hv, lv);
    xoh[idx] = hv;
    xol[idx] = lv;
}

// ---------------------------------------------------------------------------
// Launch
// ---------------------------------------------------------------------------
extern "C" void kernel_launch(void* const* d_in, const int* in_sizes, int n_in,
                              void* d_out, int out_size)
{
    const float* h      = (const float*)d_in[0];
    const float* shift  = (const float*)d_in[1];
    const float* s0     = (const float*)d_in[2];
    const float* vfirst = (const float*)d_in[3];
    const float* x_r = (const float*)d_in[4];
    const float* x_w = (const float*)d_in[5];
    const float* x_k = (const float*)d_in[6];
    const float* x_v = (const float*)d_in[7];
    const float* x_a = (const float*)d_in[8];
    const float* x_g = (const float*)d_in[9];
    const float* w0 = (const float*)d_in[10];
    const float* w1 = (const float*)d_in[11];
    const float* w2 = (const float*)d_in[12];
    const float* a0 = (const float*)d_in[13];
    const float* a1 = (const float*)d_in[14];
    const float* a2 = (const float*)d_in[15];
    const float* v0 = (const float*)d_in[16];
    const float* v1 = (const float*)d_in[17];
    const float* v2 = (const float*)d_in[18];
    const float* g1 = (const float*)d_in[19];
    const float* g2 = (const float*)d_in[20];
    const float* k_k = (const float*)d_in[21];
    const float* k_a = (const float*)d_in[22];
    const float* r_k = (const float*)d_in[23];
    const float* W_r = (const float*)d_in[24];
    const float* W_k = (const float*)d_in[25];
    const float* W_v = (const float*)d_in[26];
    const float* W_o = (const float*)d_in[27];
    const float* gnw = (const float*)d_in[28];
    const float* gnb = (const float*)d_in[29];
    float* out = (float*)d_out;

    float* S = nullptr;
    cudaGetSymbolAddress((void**)&S, g_scratch);

    float* xw    = S + (size_t)S_XW*BTC;
    float* xa    = S + (size_t)S_XA*BTC;
    float* xv    = S + (size_t)S_XV*BTC;
    float* xg    = S + (size_t)S_XG*BTC;
    float* rb    = S + (size_t)S_R*BTC;
    float* kb    = S + (size_t)S_K*BTC;
    float* vb    = S + (size_t)S_V*BTC;
    float* decay = S + (size_t)S_DECAY*BTC;
    float* asig  = S + (size_t)S_ASIG*BTC;
    float* gbuf  = S + (size_t)S_G*BTC;
    float* awb   = S + (size_t)S_AW*BTC;
    float* bwb   = S + (size_t)S_BW*BTC;
    float* kfb   = S + (size_t)S_KF*BTC;
    float* vfb   = S + (size_t)S_VF*BTC;
    float* ob    = S + (size_t)S_O*BTC;

    __nv_bfloat16* bfb = (__nv_bfloat16*)(S + BF16_BASE);
#define BF(i) (bfb + (size_t)(i)*BTC)
    __nv_bfloat16 *xrh=BF(B_XRH), *xrl=BF(B_XRL), *xkh=BF(B_XKH), *xkl=BF(B_XKL);
    __nv_bfloat16 *xvh=BF(B_XVH), *xvl=BF(B_XVL), *xoh=BF(B_XOH), *xol=BF(B_XOL);
    __nv_bfloat16 *wrh=BF(B_WRH), *wrl=BF(B_WRL), *wkh=BF(B_WKH), *wkl=BF(B_WKL);
    __nv_bfloat16 *wvh=BF(B_WVH), *wvl=BF(B_WVL), *woh=BF(B_WOH), *wol=BF(B_WOL);
#undef BF
    float* Uw = S + U_W_OFF;  float* Ua = S + U_A_OFF;
    float* Uv = S + U_V_OFF;  float* Ug = S + U_G_OFF;
    float* brg = S + BR_OFF;  float* krg = S + KR_OFF;

    cudaFuncSetAttribute(gemm_bf16x3,
                         cudaFuncAttributeMaxDynamicSharedMemorySize, GEMM_SMEM);

    // 0. weight conversions (one batched launch)
    CvtJobs cj;
    cj.x[0]=W_r; cj.hi[0]=wrh; cj.lo[0]=wrl;
    cj.x[1]=W_k; cj.hi[1]=wkh; cj.lo[1]=wkl;
    cj.x[2]=W_v; cj.hi[2]=wvh; cj.lo[2]=wvl;
    cj.x[3]=W_o; cj.hi[3]=woh; cj.lo[3]=wol;
    cvt_all_kernel<<<dim3(4096, 4), 256>>>(cj);

    // 1. token shift + mixes
    mix_kernel<<<4096, 256>>>(h, shift, x_r, x_w, x_k, x_v, x_a, x_g,
                              xrh, xrl, xw, xkh, xkl, xv, xvh, xvl, xa, xg);

    // 2. big r/k/v projections (batched HMMA launch, 3 jobs)
    GemmJobs gj;
    gj.j[0] = { xrh, xrl, wrh, wrl, rb };
    gj.j[1] = { xkh, xkl, wkh, wkl, kb };
    gj.j[2] = { xvh, xvl, wvh, wvl, vb };
    gemm_bf16x3<<<dim3(8, 16, 3), 256, GEMM_SMEM>>>(gj);

    // 3. LoRA stage 1 (batched, 5 column-tile jobs)
    Lora1Jobs lj;
    lj.j[0] = { xw, w1, Uw,  64, 0, 1 };   // tanh
    lj.j[1] = { xa, a1, Ua,  64, 0, 0 };
    lj.j[2] = { xv, v1, Uv,  32, 0, 0 };
    lj.j[3] = { xg, g1, Ug, 128, 0, 2 };   // sigmoid
    lj.j[4] = { xg, g1, Ug, 128, 64, 2 };  // sigmoid (cols 64..127)
    lora1_all_kernel<<<dim3(32, 5), 256>>>(lj);

    // 4. LoRA stage 2 + epilogues (batched, 4 jobs)
    Stage2Jobs sj;
    sj.j[0] = { Uw, w2, w0, decay, nullptr, nullptr,  64, 0 };
    sj.j[1] = { Ua, a2, a0, asig,  nullptr, nullptr,  64, 1 };
    sj.j[2] = { Uv, v2, v0, vfb,   vb,      vfirst,   32, 2 };
    sj.j[3] = { Ug, g2, nullptr, gbuf, nullptr, nullptr, 128, 3 };
    stage2_all_kernel<<<dim3(8, 64, 4), 256>>>(sj);

    // 5. kk-normalize / k lerp prep + per-step scalars
    prep_kernel<<<BT*HH/4, 256>>>(kb, rb, asig, k_k, k_a, awb, bwb, kfb, brg, krg);

    // 6. WKV7 recurrence (v-split x4, cp.async ring pipeline)
    wkv_kernel<<<BB*HH*4, 128>>>(rb, kfb, vfb, decay, awb, bwb, brg, krg, s0, ob);

    // 7. group norm + bonus + gate
    gn_kernel<<<BT*HH/4, 256>>>(ob, rb, kfb, vfb, gbuf, r_k, gnw, gnb, xoh, xol);

    // 8. output projection (single job)
    GemmJobs oj;
    oj.j[0] = { xoh, xol, woh, wol, out };
    oj.j[1] = oj.j[0];
    oj.j[2] = oj.j[0];
    gemm_bf16x3<<<dim3(8, 16, 1), 256, GEMM_SMEM>>>(oj);
}